// round 15
// baseline (speedup 1.0000x reference)
#include <cuda_runtime.h>
#include <cuda_bf16.h>
#include <math_constants.h>
#include <cstdint>
#include <cstddef>

#define T_DIM 2048
#define E_DIM 1024
#define M_DIM 32768
#define H_DIM 16
#define D_DIM 64
#define KCAND 12

// ---------------- device scratch ----------------
__device__ float g_qkv[T_DIM * 3 * E_DIM];
__device__ float g_y[T_DIM * E_DIM];
__device__ __nv_bfloat16 g_Sbf[(size_t)T_DIM * M_DIM];   // 128 MB coarse scores
__device__ float g_mknorm[M_DIM];
__device__ int   g_cand[T_DIM * KCAND];
__device__ int   g_idx[T_DIM * 3];
__device__ float g_comb[T_DIM * E_DIM];
__device__ __nv_bfloat16 g_qbf[T_DIM * E_DIM];
__device__ __nv_bfloat16 g_mkbf[(size_t)M_DIM * E_DIM];

__device__ __forceinline__ uint32_t smem_u32(const void* p) {
    return (uint32_t)__cvta_generic_to_shared(p);
}
__device__ __forceinline__ uint32_t f2tf32(float f) {
    uint32_t u;
    asm("cvt.rna.tf32.f32 %0,%1;" : "=r"(u) : "f"(f));
    return u;
}
__device__ __forceinline__ float f2tf32f(float f) {
    return __uint_as_float(f2tf32(f));
}

// ---------------- fp32 SGEMM (NT) — ranking-exact q path ----
template <int WRITE_BF16>
__global__ void __launch_bounds__(256)
sgemm_nt(const float* __restrict__ A, int lda,
         const float* __restrict__ B, int ldb,
         float* __restrict__ C, int ldc, int K) {
    __shared__ float As[8][132];
    __shared__ float Bs[8][132];
    const int tid = threadIdx.x;
    const int mBase = blockIdx.y * 128;
    const int nBase = blockIdx.x * 128;
    const int lr = tid >> 1;
    const int lc = (tid & 1) << 2;
    const float* Ag = A + (size_t)(mBase + lr) * lda + lc;
    const float* Bg = B + (size_t)(nBase + lr) * ldb + lc;
    const int tm = tid >> 4;
    const int tn = tid & 15;

    float acc[8][8];
#pragma unroll
    for (int i = 0; i < 8; i++)
#pragma unroll
        for (int j = 0; j < 8; j++) acc[i][j] = 0.0f;

    for (int k0 = 0; k0 < K; k0 += 8) {
        float4 av = *(const float4*)(Ag + k0);
        float4 bv = *(const float4*)(Bg + k0);
        __syncthreads();
        As[lc + 0][lr] = av.x; As[lc + 1][lr] = av.y;
        As[lc + 2][lr] = av.z; As[lc + 3][lr] = av.w;
        Bs[lc + 0][lr] = bv.x; Bs[lc + 1][lr] = bv.y;
        Bs[lc + 2][lr] = bv.z; Bs[lc + 3][lr] = bv.w;
        __syncthreads();
#pragma unroll
        for (int kk = 0; kk < 8; kk++) {
            float a[8], b[8];
            *(float4*)&a[0] = *(const float4*)&As[kk][tm * 8];
            *(float4*)&a[4] = *(const float4*)&As[kk][tm * 8 + 4];
            *(float4*)&b[0] = *(const float4*)&Bs[kk][tn * 8];
            *(float4*)&b[4] = *(const float4*)&Bs[kk][tn * 8 + 4];
#pragma unroll
            for (int i = 0; i < 8; i++)
#pragma unroll
                for (int j = 0; j < 8; j++)
                    acc[i][j] += a[i] * b[j];
        }
    }

#pragma unroll
    for (int i = 0; i < 8; i++) {
        int row = mBase + tm * 8 + i;
        size_t roff = (size_t)row * ldc + nBase + tn * 8;
#pragma unroll
        for (int j = 0; j < 8; j += 4) {
            float4 v;
            v.x = acc[i][j]; v.y = acc[i][j + 1];
            v.z = acc[i][j + 2]; v.w = acc[i][j + 3];
            *(float4*)&C[roff + j] = v;
            if (WRITE_BF16) {
                __nv_bfloat162* o =
                    (__nv_bfloat162*)&g_qbf[(size_t)row * 1024 + nBase + tn * 8 + j];
                o[0] = __float22bfloat162_rn(make_float2(v.x, v.y));
                o[1] = __float22bfloat162_rn(make_float2(v.z, v.w));
            }
        }
    }
}

// ---------------- tf32 tensor-core NT GEMM: C = A B^T ----------------
__global__ void __launch_bounds__(256)
gemm_tf32_nt(const float* __restrict__ A, int lda,
             const float* __restrict__ B, int ldb,
             float* __restrict__ C, int ldc, int K) {
    __shared__ float As[2][128 * 20];
    __shared__ float Bs[2][128 * 20];
    const int tid = threadIdx.x;
    const int mBase = blockIdx.y * 128;
    const int nBase = blockIdx.x * 128;
    const int lrow = tid >> 2;
    const int k4 = (tid & 3) * 4;
    const int warp = tid >> 5, lane = tid & 31;
    const int wm = warp & 3, wn = warp >> 2;

    float acc[2][8][4];
#pragma unroll
    for (int a = 0; a < 2; a++)
#pragma unroll
        for (int b = 0; b < 8; b++)
#pragma unroll
            for (int c = 0; c < 4; c++) acc[a][b][c] = 0.0f;

#define GL_STAGE(st, k0)                                                        \
    {                                                                           \
        _Pragma("unroll")                                                       \
        for (int half = 0; half < 2; half++) {                                  \
            int row = lrow + half * 64;                                         \
            uint32_t sa = smem_u32(&As[st][row * 20 + k4]);                     \
            const void* ga = A + (size_t)(mBase + row) * lda + (k0) + k4;       \
            asm volatile("cp.async.cg.shared.global [%0],[%1],16;\n"            \
                         :: "r"(sa), "l"(ga));                                  \
            uint32_t sb = smem_u32(&Bs[st][row * 20 + k4]);                     \
            const void* gb = B + (size_t)(nBase + row) * ldb + (k0) + k4;       \
            asm volatile("cp.async.cg.shared.global [%0],[%1],16;\n"            \
                         :: "r"(sb), "l"(gb));                                  \
        }                                                                       \
        asm volatile("cp.async.commit_group;\n");                               \
    }

    GL_STAGE(0, 0)
    const int KS = K / 16;
    for (int ks = 0; ks < KS; ks++) {
        if (ks + 1 < KS) {
            GL_STAGE((ks + 1) & 1, (ks + 1) * 16)
            asm volatile("cp.async.wait_group 1;\n");
        } else {
            asm volatile("cp.async.wait_group 0;\n");
        }
        __syncthreads();
        const float* as = As[ks & 1];
        const float* bs = Bs[ks & 1];
#pragma unroll
        for (int kk = 0; kk < 16; kk += 8) {
            uint32_t af[2][4], bf[8][2];
#pragma unroll
            for (int mt = 0; mt < 2; mt++) {
                int r0 = wm * 32 + mt * 16 + (lane >> 2);
                int c0 = kk + (lane & 3);
                af[mt][0] = f2tf32(as[r0 * 20 + c0]);
                af[mt][1] = f2tf32(as[(r0 + 8) * 20 + c0]);
                af[mt][2] = f2tf32(as[r0 * 20 + c0 + 4]);
                af[mt][3] = f2tf32(as[(r0 + 8) * 20 + c0 + 4]);
            }
#pragma unroll
            for (int nt = 0; nt < 8; nt++) {
                int n0 = wn * 64 + nt * 8 + (lane >> 2);
                int c0 = kk + (lane & 3);
                bf[nt][0] = f2tf32(bs[n0 * 20 + c0]);
                bf[nt][1] = f2tf32(bs[n0 * 20 + c0 + 4]);
            }
#pragma unroll
            for (int mt = 0; mt < 2; mt++)
#pragma unroll
                for (int nt = 0; nt < 8; nt++)
                    asm volatile(
                        "mma.sync.aligned.m16n8k8.row.col.f32.tf32.tf32.f32 "
                        "{%0,%1,%2,%3},{%4,%5,%6,%7},{%8,%9},{%0,%1,%2,%3};\n"
                        : "+f"(acc[mt][nt][0]), "+f"(acc[mt][nt][1]),
                          "+f"(acc[mt][nt][2]), "+f"(acc[mt][nt][3])
                        : "r"(af[mt][0]), "r"(af[mt][1]),
                          "r"(af[mt][2]), "r"(af[mt][3]),
                          "r"(bf[nt][0]), "r"(bf[nt][1]));
        }
        __syncthreads();
    }

    const int r = lane >> 2, c = (lane & 3) * 2;
#pragma unroll
    for (int mt = 0; mt < 2; mt++) {
#pragma unroll
        for (int nt = 0; nt < 8; nt++) {
            int row0 = mBase + wm * 32 + mt * 16 + r;
            int col = nBase + wn * 64 + nt * 8 + c;
            *(float2*)&C[(size_t)row0 * ldc + col] =
                make_float2(acc[mt][nt][0], acc[mt][nt][1]);
            *(float2*)&C[(size_t)(row0 + 8) * ldc + col] =
                make_float2(acc[mt][nt][2], acc[mt][nt][3]);
        }
    }
#undef GL_STAGE
}

// ---------------- fused: mem-key bf16 convert + |mk|^2 ----
__global__ void __launch_bounds__(256)
cvtmk_norm_kernel(const float* __restrict__ mem_db,
                  __nv_bfloat16* __restrict__ kb) {
    __shared__ float ws[8];
    const int row = blockIdx.x;
    const int tid = threadIdx.x;
    float4 v = ((const float4*)(mem_db + (size_t)row * 2048))[tid];
    __nv_bfloat162* o = (__nv_bfloat162*)(kb + (size_t)row * 1024 + tid * 4);
    o[0] = __float22bfloat162_rn(make_float2(v.x, v.y));
    o[1] = __float22bfloat162_rn(make_float2(v.z, v.w));
    float s = v.x * v.x + v.y * v.y + v.z * v.z + v.w * v.w;
#pragma unroll
    for (int off = 16; off; off >>= 1) s += __shfl_xor_sync(0xffffffffu, s, off);
    if ((tid & 31) == 0) ws[tid >> 5] = s;
    __syncthreads();
    if (tid == 0) {
        float t = 0.0f;
#pragma unroll
        for (int w = 0; w < 8; w++) t += ws[w];
        g_mknorm[row] = t;
    }
}

// ---------------- bf16 NT GEMM (d2 coarse scores) -> bf16 S --------------
#define SROW 72                              // 64 data + 8 pad bf16 elems
#define STAGE_BYTES (128 * SROW * 2)         // 18432 B per operand per stage

__global__ void __launch_bounds__(256)
gemm_bf16_nt(const __nv_bfloat16* __restrict__ A,
             const __nv_bfloat16* __restrict__ B,
             __nv_bfloat16* __restrict__ C,
             const float* __restrict__ bias) {
    extern __shared__ __align__(16) char gsm[];
    __nv_bfloat16* Abuf = (__nv_bfloat16*)gsm;
    __nv_bfloat16* Bbuf = (__nv_bfloat16*)(gsm + 2 * STAGE_BYTES);

    const int tid = threadIdx.x;
    const int mBase = blockIdx.y * 128;
    const int nBase = blockIdx.x * 128;
    const int warp = tid >> 5, lane = tid & 31;
    const int wm = warp & 1, wn = warp >> 1;

    float acc[4][4][4];
#pragma unroll
    for (int a = 0; a < 4; a++)
#pragma unroll
        for (int b = 0; b < 4; b++)
#pragma unroll
            for (int c = 0; c < 4; c++) acc[a][b][c] = 0.0f;

#define LOAD_STAGE(ks)                                                          \
    {                                                                           \
        const int _st = (ks) & 1;                                               \
        __nv_bfloat16* _as = Abuf + _st * (128 * SROW);                         \
        __nv_bfloat16* _bs = Bbuf + _st * (128 * SROW);                         \
        _Pragma("unroll")                                                       \
        for (int _i = 0; _i < 4; _i++) {                                        \
            int _idx = tid + _i * 256;                                          \
            int _row = _idx >> 3, _ch = _idx & 7;                               \
            uint32_t _sa = smem_u32(_as + _row * SROW + _ch * 8);               \
            const void* _ga = A + (size_t)(mBase + _row) * 1024 + (ks) * 64 + _ch * 8; \
            asm volatile("cp.async.cg.shared.global [%0],[%1],16;\n"            \
                         :: "r"(_sa), "l"(_ga));                                \
            uint32_t _sb = smem_u32(_bs + _row * SROW + _ch * 8);               \
            const void* _gb = B + (size_t)(nBase + _row) * 1024 + (ks) * 64 + _ch * 8; \
            asm volatile("cp.async.cg.shared.global [%0],[%1],16;\n"            \
                         :: "r"(_sb), "l"(_gb));                                \
        }                                                                       \
        asm volatile("cp.async.commit_group;\n");                               \
    }

    LOAD_STAGE(0)

    for (int ks = 0; ks < 16; ks++) {
        if (ks + 1 < 16) {
            LOAD_STAGE(ks + 1)
            asm volatile("cp.async.wait_group 1;\n");
        } else {
            asm volatile("cp.async.wait_group 0;\n");
        }
        __syncthreads();
        const __nv_bfloat16* as = Abuf + (ks & 1) * (128 * SROW);
        const __nv_bfloat16* bs = Bbuf + (ks & 1) * (128 * SROW);
#pragma unroll
        for (int kk = 0; kk < 64; kk += 16) {
            uint32_t af[4][4], bf[4][2];
#pragma unroll
            for (int mt = 0; mt < 4; mt++) {
                int base = wm * 64 + mt * 16;
                int r = lane & 7;
                int sel = lane >> 3;
                int row = base + ((sel & 1) ? 8 : 0) + r;
                int col = kk + ((sel & 2) ? 8 : 0);
                uint32_t addr = smem_u32(&as[row * SROW + col]);
                asm volatile(
                    "ldmatrix.sync.aligned.m8n8.x4.shared.b16 {%0,%1,%2,%3},[%4];\n"
                    : "=r"(af[mt][0]), "=r"(af[mt][1]),
                      "=r"(af[mt][2]), "=r"(af[mt][3])
                    : "r"(addr));
            }
#pragma unroll
            for (int np = 0; np < 2; np++) {
                int r = lane & 7;
                int sel = lane >> 3;
                int row = wn * 32 + np * 16 + ((sel >> 1) ? 8 : 0) + r;
                int col = kk + ((sel & 1) ? 8 : 0);
                uint32_t addr = smem_u32(&bs[row * SROW + col]);
                asm volatile(
                    "ldmatrix.sync.aligned.m8n8.x4.shared.b16 {%0,%1,%2,%3},[%4];\n"
                    : "=r"(bf[2 * np][0]), "=r"(bf[2 * np][1]),
                      "=r"(bf[2 * np + 1][0]), "=r"(bf[2 * np + 1][1])
                    : "r"(addr));
            }
#pragma unroll
            for (int mt = 0; mt < 4; mt++)
#pragma unroll
                for (int nt = 0; nt < 4; nt++)
                    asm volatile(
                        "mma.sync.aligned.m16n8k16.row.col.f32.bf16.bf16.f32 "
                        "{%0,%1,%2,%3},{%4,%5,%6,%7},{%8,%9},{%0,%1,%2,%3};\n"
                        : "+f"(acc[mt][nt][0]), "+f"(acc[mt][nt][1]),
                          "+f"(acc[mt][nt][2]), "+f"(acc[mt][nt][3])
                        : "r"(af[mt][0]), "r"(af[mt][1]),
                          "r"(af[mt][2]), "r"(af[mt][3]),
                          "r"(bf[nt][0]), "r"(bf[nt][1]));
        }
        __syncthreads();
    }

    const int r = lane >> 2, c = (lane & 3) * 2;
#pragma unroll
    for (int mt = 0; mt < 4; mt++) {
#pragma unroll
        for (int nt = 0; nt < 4; nt++) {
            int row0 = mBase + wm * 64 + mt * 16 + r;
            int col = nBase + wn * 32 + nt * 8 + c;
            float b0 = bias[col], b1 = bias[col + 1];
            size_t o0 = (size_t)row0 * M_DIM + col;
            *(__nv_bfloat162*)&C[o0] = __float22bfloat162_rn(
                make_float2(-2.0f * acc[mt][nt][0] + b0,
                            -2.0f * acc[mt][nt][1] + b1));
            size_t o1 = o0 + (size_t)8 * M_DIM;
            *(__nv_bfloat162*)&C[o1] = __float22bfloat162_rn(
                make_float2(-2.0f * acc[mt][nt][2] + b0,
                            -2.0f * acc[mt][nt][3] + b1));
        }
    }
#undef LOAD_STAGE
}

// ---------------- causal flash attention, warp-local softmax --------------
__global__ void __launch_bounds__(256, 2)
flash_tf32_kernel(const float* __restrict__ qkv, float* __restrict__ y) {
    extern __shared__ float sm[];

    const int h = blockIdx.y;
    const int qt = blockIdx.x;
    const int tid = threadIdx.x;
    const int qbase = qt * 128;
    const int LDQ = 3 * E_DIM;
    const int warp = tid >> 5, lane = tid & 31;
    const int fr = lane >> 2, fc = lane & 3;
    const int gr0 = qbase + warp * 16 + fr;

    uint32_t qf[8][4];
    {
        const float* q0p = &qkv[(size_t)gr0 * LDQ + h * 64];
        const float* q1p = q0p + 8 * LDQ;
#pragma unroll
        for (int ks = 0; ks < 8; ks++) {
            qf[ks][0] = f2tf32(q0p[ks * 8 + fc]);
            qf[ks][1] = f2tf32(q1p[ks * 8 + fc]);
            qf[ks][2] = f2tf32(q0p[ks * 8 + fc + 4]);
            qf[ks][3] = f2tf32(q1p[ks * 8 + fc + 4]);
        }
    }

    float m0 = -CUDART_INF_F, m1 = -CUDART_INF_F;
    float l0 = 0.0f, l1 = 0.0f;
    float acc[8][4];
#pragma unroll
    for (int nt = 0; nt < 8; nt++)
#pragma unroll
        for (int c = 0; c < 4; c++) acc[nt][c] = 0.0f;

    const int nkt = 2 * qt + 2;

#define FL_LOAD(kt)                                                             \
    {                                                                           \
        float* _ks = sm + ((kt) & 1) * (2 * 64 * 68);                           \
        float* _vs = _ks + 64 * 68;                                             \
        const int _kb = (kt) * 64;                                              \
        _Pragma("unroll")                                                       \
        for (int _i = 0; _i < 4; _i++) {                                        \
            int _idx = tid + _i * 256;                                          \
            int _r = _idx >> 4, _c4 = (_idx & 15) << 2;                         \
            const float* _src = qkv + (size_t)(_kb + _r) * LDQ + h * 64 + _c4;  \
            asm volatile("cp.async.cg.shared.global [%0],[%1],16;\n"            \
                :: "r"(smem_u32(_ks + _r * 68 + _c4)), "l"(_src + E_DIM));      \
            asm volatile("cp.async.cg.shared.global [%0],[%1],16;\n"            \
                :: "r"(smem_u32(_vs + _r * 68 + _c4)), "l"(_src + 2 * E_DIM));  \
        }                                                                       \
        asm volatile("cp.async.commit_group;\n");                               \
    }

    FL_LOAD(0)
    FL_LOAD(1)

    for (int kt = 0; kt < nkt; kt++) {
        const int kbase = kt * 64;
        if (kt + 1 < nkt) asm volatile("cp.async.wait_group 1;\n");
        else              asm volatile("cp.async.wait_group 0;\n");
        __syncthreads();
        const float* Ks = sm + (kt & 1) * (2 * 64 * 68);
        const float* Vs = Ks + 64 * 68;

        float p[8][4];
#pragma unroll
        for (int nt = 0; nt < 8; nt++)
#pragma unroll
            for (int c = 0; c < 4; c++) p[nt][c] = 0.0f;
#pragma unroll
        for (int ks = 0; ks < 8; ks++) {
            const int kc = ks * 8;
#pragma unroll
            for (int nt = 0; nt < 8; nt++) {
                int n0 = nt * 8 + fr;
                uint32_t b0 = __float_as_uint(Ks[n0 * 68 + kc + fc]);
                uint32_t b1 = __float_as_uint(Ks[n0 * 68 + kc + fc + 4]);
                asm volatile(
                    "mma.sync.aligned.m16n8k8.row.col.f32.tf32.tf32.f32 "
                    "{%0,%1,%2,%3},{%4,%5,%6,%7},{%8,%9},{%0,%1,%2,%3};\n"
                    : "+f"(p[nt][0]), "+f"(p[nt][1]),
                      "+f"(p[nt][2]), "+f"(p[nt][3])
                    : "r"(qf[ks][0]), "r"(qf[ks][1]),
                      "r"(qf[ks][2]), "r"(qf[ks][3]),
                      "r"(b0), "r"(b1));
            }
        }
#pragma unroll
        for (int nt = 0; nt < 8; nt++) {
            p[nt][0] *= 0.125f; p[nt][1] *= 0.125f;
            p[nt][2] *= 0.125f; p[nt][3] *= 0.125f;
        }
        if (kbase + 63 > qbase + warp * 16) {
#pragma unroll
            for (int nt = 0; nt < 8; nt++) {
                int c0 = kbase + nt * 8 + 2 * fc;
                if (c0 > gr0)     p[nt][0] = -CUDART_INF_F;
                if (c0 + 1 > gr0) p[nt][1] = -CUDART_INF_F;
                if (c0 > gr0 + 8)     p[nt][2] = -CUDART_INF_F;
                if (c0 + 1 > gr0 + 8) p[nt][3] = -CUDART_INF_F;
            }
        }
        float mx0 = -CUDART_INF_F, mx1 = -CUDART_INF_F;
#pragma unroll
        for (int nt = 0; nt < 8; nt++) {
            mx0 = fmaxf(mx0, fmaxf(p[nt][0], p[nt][1]));
            mx1 = fmaxf(mx1, fmaxf(p[nt][2], p[nt][3]));
        }
        mx0 = fmaxf(mx0, __shfl_xor_sync(0xffffffffu, mx0, 1));
        mx0 = fmaxf(mx0, __shfl_xor_sync(0xffffffffu, mx0, 2));
        mx1 = fmaxf(mx1, __shfl_xor_sync(0xffffffffu, mx1, 1));
        mx1 = fmaxf(mx1, __shfl_xor_sync(0xffffffffu, mx1, 2));
        float mn0 = fmaxf(m0, mx0), mn1 = fmaxf(m1, mx1);
        float cor0 = __expf(m0 - mn0), cor1 = __expf(m1 - mn1);
        m0 = mn0; m1 = mn1;
        float s0 = 0.0f, s1 = 0.0f;
#pragma unroll
        for (int nt = 0; nt < 8; nt++) {
            p[nt][0] = __expf(p[nt][0] - mn0);
            p[nt][1] = __expf(p[nt][1] - mn0);
            p[nt][2] = __expf(p[nt][2] - mn1);
            p[nt][3] = __expf(p[nt][3] - mn1);
            s0 += p[nt][0] + p[nt][1];
            s1 += p[nt][2] + p[nt][3];
        }
        s0 += __shfl_xor_sync(0xffffffffu, s0, 1);
        s0 += __shfl_xor_sync(0xffffffffu, s0, 2);
        s1 += __shfl_xor_sync(0xffffffffu, s1, 1);
        s1 += __shfl_xor_sync(0xffffffffu, s1, 2);
        l0 = l0 * cor0 + s0;
        l1 = l1 * cor1 + s1;
#pragma unroll
        for (int nt = 0; nt < 8; nt++) {
            acc[nt][0] *= cor0; acc[nt][1] *= cor0;
            acc[nt][2] *= cor1; acc[nt][3] *= cor1;
        }
        const int srcA = (lane & ~3) | (fc >> 1);
        const int srcC = srcA + 2;
        const bool odd = fc & 1;
#pragma unroll
        for (int ks = 0; ks < 8; ks++) {
            float t00 = __shfl_sync(0xffffffffu, p[ks][0], srcA);
            float t01 = __shfl_sync(0xffffffffu, p[ks][1], srcA);
            float t10 = __shfl_sync(0xffffffffu, p[ks][2], srcA);
            float t11 = __shfl_sync(0xffffffffu, p[ks][3], srcA);
            float u00 = __shfl_sync(0xffffffffu, p[ks][0], srcC);
            float u01 = __shfl_sync(0xffffffffu, p[ks][1], srcC);
            float u10 = __shfl_sync(0xffffffffu, p[ks][2], srcC);
            float u11 = __shfl_sync(0xffffffffu, p[ks][3], srcC);
            uint32_t a0 = __float_as_uint(odd ? t01 : t00);
            uint32_t a1 = __float_as_uint(odd ? t11 : t10);
            uint32_t a2 = __float_as_uint(odd ? u01 : u00);
            uint32_t a3 = __float_as_uint(odd ? u11 : u10);
            const int kc = ks * 8;
#pragma unroll
            for (int nt = 0; nt < 8; nt++) {
                int n0 = nt * 8 + fr;
                uint32_t b0 = __float_as_uint(Vs[(kc + fc) * 68 + n0]);
                uint32_t b1 = __float_as_uint(Vs[(kc + fc + 4) * 68 + n0]);
                asm volatile(
                    "mma.sync.aligned.m16n8k8.row.col.f32.tf32.tf32.f32 "
                    "{%0,%1,%2,%3},{%4,%5,%6,%7},{%8,%9},{%0,%1,%2,%3};\n"
                    : "+f"(acc[nt][0]), "+f"(acc[nt][1]),
                      "+f"(acc[nt][2]), "+f"(acc[nt][3])
                    : "r"(a0), "r"(a1), "r"(a2), "r"(a3),
                      "r"(b0), "r"(b1));
            }
        }
        __syncthreads();
        if (kt + 2 < nkt) FL_LOAD(kt + 2)
    }

    const float li0 = 1.0f / l0, li1 = 1.0f / l1;
#pragma unroll
    for (int nt = 0; nt < 8; nt++) {
        int c0 = h * 64 + nt * 8 + 2 * fc;
        *(float2*)&y[(size_t)gr0 * E_DIM + c0] =
            make_float2(acc[nt][0] * li0, acc[nt][1] * li0);
        *(float2*)&y[(size_t)(gr0 + 8) * E_DIM + c0] =
            make_float2(acc[nt][2] * li1, acc[nt][3] * li1);
    }
#undef FL_LOAD
}

// ---------------- candidate top-12 (bf16 coarse scores) ----------
__device__ __forceinline__ bool lt_pair(float v, int i, float w, int j) {
    return (v < w) || (v == w && i < j);
}

__global__ void __launch_bounds__(256)
topk_kernel(const __nv_bfloat16* __restrict__ S) {
    __shared__ float sv[256][KCAND];
    __shared__ int   si[256][KCAND];
    const int t = blockIdx.x;
    const int tid = threadIdx.x;
    const __nv_bfloat16* row = S + (size_t)t * M_DIM;
    float v[KCAND];
    int ix[KCAND];
#pragma unroll
    for (int k = 0; k < KCAND; k++) { v[k] = CUDART_INF_F; ix[k] = 0x7fffffff; }

#define TK_INSERT(val, idx)                                                     \
    if (lt_pair((val), (idx), v[KCAND - 1], ix[KCAND - 1])) {                   \
        v[KCAND - 1] = (val); ix[KCAND - 1] = (idx);                            \
        _Pragma("unroll")                                                       \
        for (int k = KCAND - 1; k > 0; k--) {                                   \
            if (lt_pair(v[k], ix[k], v[k - 1], ix[k - 1])) {                    \
                float tv = v[k]; v[k] = v[k - 1]; v[k - 1] = tv;                \
                int ti = ix[k]; ix[k] = ix[k - 1]; ix[k - 1] = ti;              \
            } else break;                                                       \
        }                                                                       \
    }

    for (int j = tid * 8; j < M_DIM; j += 2048) {
        uint4 raw = *(const uint4*)&row[j];
        const uint32_t w[4] = {raw.x, raw.y, raw.z, raw.w};
#pragma unroll
        for (int q = 0; q < 4; q++) {
            float2 pr = __bfloat1622float2(*(const __nv_bfloat162*)&w[q]);
            TK_INSERT(pr.x, j + 2 * q)
            TK_INSERT(pr.y, j + 2 * q + 1)
        }
    }
#pragma unroll
    for (int k = 0; k < KCAND; k++) { sv[tid][k] = v[k]; si[tid][k] = ix[k]; }
    for (int s = 128; s > 0; s >>= 1) {
        __syncthreads();
        if (tid < s) {
#pragma unroll
            for (int k = 0; k < KCAND; k++) {
                float val = sv[tid + s][k];
                int idx = si[tid + s][k];
                TK_INSERT(val, idx)
            }
#pragma unroll
            for (int k = 0; k < KCAND; k++) { sv[tid][k] = v[k]; si[tid][k] = ix[k]; }
        }
    }
    if (tid == 0) {
#pragma unroll
        for (int k = 0; k < KCAND; k++) g_cand[t * KCAND + k] = ix[k];
    }
#undef TK_INSERT
}

// ---------------- exact fp32 rescore of 12 candidates -> top-3 ------------
__global__ void __launch_bounds__(384)
rescore_kernel(const float* __restrict__ qkv,
               const float* __restrict__ mem_db,
               const float* __restrict__ mknorm) {
    __shared__ float sc[KCAND];
    __shared__ int   sidx[KCAND];
    const int t = blockIdx.x;
    const int w = threadIdx.x >> 5;         // 0..11
    const int lane = threadIdx.x & 31;
    const int cand = g_cand[t * KCAND + w];

    const float* qrow = qkv + (size_t)t * 3 * E_DIM;
    const float* krow = mem_db + (size_t)cand * 2 * E_DIM;
    float dot = 0.0f;
#pragma unroll
    for (int c = 0; c < 8; c++) {
        int e = (lane + c * 32) * 4;
        float4 qv = *(const float4*)&qrow[e];
        float4 kv = *(const float4*)&krow[e];
        dot += qv.x * kv.x + qv.y * kv.y + qv.z * kv.z + qv.w * kv.w;
    }
#pragma unroll
    for (int o = 16; o; o >>= 1) dot += __shfl_xor_sync(0xffffffffu, dot, o);
    if (lane == 0) {
        sc[w] = mknorm[cand] - 2.0f * dot;
        sidx[w] = cand;
    }
    __syncthreads();
    if (threadIdx.x == 0) {
        float v0 = CUDART_INF_F, v1 = CUDART_INF_F, v2 = CUDART_INF_F;
        int i0 = 0x7fffffff, i1 = 0x7fffffff, i2 = 0x7fffffff;
#pragma unroll
        for (int k = 0; k < KCAND; k++) {
            float val = sc[k]; int idx = sidx[k];
            if (lt_pair(val, idx, v2, i2)) {
                if (lt_pair(val, idx, v1, i1)) {
                    v2 = v1; i2 = i1;
                    if (lt_pair(val, idx, v0, i0)) {
                        v1 = v0; i1 = i0; v0 = val; i0 = idx;
                    } else { v1 = val; i1 = idx; }
                } else { v2 = val; i2 = idx; }
            }
        }
        g_idx[t * 3 + 0] = i0;
        g_idx[t * 3 + 1] = i1;
        g_idx[t * 3 + 2] = i2;
    }
}

// ---------------- gather + 3-way mem softmax + gated combine -------------
__global__ void __launch_bounds__(512)
memattn_kernel(const float* __restrict__ qkv,
               const float* __restrict__ mem_db,
               const float* __restrict__ y,
               const float* __restrict__ gate) {
    const int t = blockIdx.x;
    const int h = threadIdx.x >> 5;
    const int lane = threadIdx.x & 31;
    int id0 = g_idx[t * 3 + 0];
    int id1 = g_idx[t * 3 + 1];
    int id2 = g_idx[t * 3 + 2];
    const int d0 = lane * 2;
    size_t qoff = (size_t)t * 3 * E_DIM + h * 64 + d0;
    float q0 = qkv[qoff], q1 = qkv[qoff + 1];

    const float* k0p = mem_db + (size_t)id0 * 2 * E_DIM + h * 64;
    const float* k1p = mem_db + (size_t)id1 * 2 * E_DIM + h * 64;
    const float* k2p = mem_db + (size_t)id2 * 2 * E_DIM + h * 64;
    float s0 = q0 * k0p[d0] + q1 * k0p[d0 + 1];
    float s1 = q0 * k1p[d0] + q1 * k1p[d0 + 1];
    float s2 = q0 * k2p[d0] + q1 * k2p[d0 + 1];
#pragma unroll
    for (int o = 16; o; o >>= 1) {
        s0 += __shfl_xor_sync(0xffffffffu, s0, o);
        s1 += __shfl_xor_sync(0xffffffffu, s1, o);
        s2 += __shfl_xor_sync(0xffffffffu, s2, o);
    }
    s0 *= 4096.0f; s1 *= 4096.0f; s2 *= 4096.0f;
    float m = fmaxf(s0, fmaxf(s1, s2));
    float e0 = expf(s0 - m), e1 = expf(s1 - m), e2 = expf(s2 - m);
    float inv = 1.0f / (e0 + e1 + e2);
    e0 *= inv; e1 *= inv; e2 *= inv;

    const float* v0p = k0p + E_DIM;
    const float* v1p = k1p + E_DIM;
    const float* v2p = k2p + E_DIM;
    float o0 = e0 * v0p[d0] + e1 * v1p[d0] + e2 * v2p[d0];
    float o1 = e0 * v0p[d0 + 1] + e1 * v1p[d0 + 1] + e2 * v2p[d0 + 1];

    float g = gate[h];
    size_t off = (size_t)t * E_DIM + h * 64 + d0;
    g_comb[off]     = o0 * g + y[off] * (1.0f - g);
    g_comb[off + 1] = o1 * g + y[off + 1] * (1.0f - g);
}

// ---------------- launch (fork/join concurrency) ----------------
extern "C" void kernel_launch(void* const* d_in, const int* in_sizes, int n_in,
                              void* d_out, int out_size) {
    const float* x = nullptr;
    const float* mem_db = nullptr;
    const float* W_attn = nullptr;
    const float* W_proj = nullptr;
    const float* gate = nullptr;
    for (int i = 0; i < n_in; i++) {
        switch (in_sizes[i]) {
            case 2048 * 1024:       x      = (const float*)d_in[i]; break;
            case 32768 * 2048:      mem_db = (const float*)d_in[i]; break;
            case 3072 * 1024:       W_attn = (const float*)d_in[i]; break;
            case 1024 * 1024:       W_proj = (const float*)d_in[i]; break;
            case 16:                gate   = (const float*)d_in[i]; break;
            default: break;
        }
    }
    float* out = (float*)d_out;

    void *p_qkv, *p_y, *p_S, *p_comb, *p_mkn, *p_qbf, *p_mkbf;
    cudaGetSymbolAddress(&p_qkv, g_qkv);
    cudaGetSymbolAddress(&p_y, g_y);
    cudaGetSymbolAddress(&p_S, g_Sbf);
    cudaGetSymbolAddress(&p_comb, g_comb);
    cudaGetSymbolAddress(&p_mkn, g_mknorm);
    cudaGetSymbolAddress(&p_qbf, g_qbf);
    cudaGetSymbolAddress(&p_mkbf, g_mkbf);
    float* qkv = (float*)p_qkv;
    float* y = (float*)p_y;
    __nv_bfloat16* S = (__nv_bfloat16*)p_S;
    float* comb = (float*)p_comb;
    float* mkn = (float*)p_mkn;
    __nv_bfloat16* qbf = (__nv_bfloat16*)p_qbf;
    __nv_bfloat16* mkbf = (__nv_bfloat16*)p_mkbf;

    static cudaStream_t s2 = nullptr;
    static cudaEvent_t evFork = nullptr, evQ = nullptr, evJoin = nullptr;
    if (s2 == nullptr) {
        cudaStreamCreateWithFlags(&s2, cudaStreamNonBlocking);
        cudaEventCreateWithFlags(&evFork, cudaEventDisableTiming);
        cudaEventCreateWithFlags(&evQ, cudaEventDisableTiming);
        cudaEventCreateWithFlags(&evJoin, cudaEventDisableTiming);
    }

    const int FLASH_SMEM = 4 * 64 * 68 * 4;   // 69632 B
    cudaFuncSetAttribute(flash_tf32_kernel,
                         cudaFuncAttributeMaxDynamicSharedMemorySize, FLASH_SMEM);
    const int GEMM_SMEM = 4 * STAGE_BYTES;    // 73728 B (2-stage, K-chunk 64)
    cudaFuncSetAttribute(gemm_bf16_nt,
                         cudaFuncAttributeMaxDynamicSharedMemorySize, GEMM_SMEM);

    // ---- fork side stream s2 off the capture (default) stream ----
    cudaEventRecord(evFork, 0);
    cudaStreamWaitEvent(s2, evFork, 0);

    // s2: mem-key convert + norms (needs only mem_db)
    cvtmk_norm_kernel<<<M_DIM, 256, 0, s2>>>(mem_db, mkbf);

    // s0: q = x @ W_attn[0:1024]^T  (fp32 — also emits q bf16)
    sgemm_nt<1><<<dim3(1024 / 128, 2048 / 128), 256>>>(
        x, E_DIM, W_attn, E_DIM, qkv, 3 * E_DIM, E_DIM);
    cudaEventRecord(evQ, 0);

    // s0: k,v = x @ W_attn[1024:3072]^T  (tf32)
    gemm_tf32_nt<<<dim3(2048 / 128, 2048 / 128), 256>>>(
        x, E_DIM, W_attn + (size_t)E_DIM * E_DIM, E_DIM,
        qkv + E_DIM, 3 * E_DIM, E_DIM);

    // s0: causal attention -> y  (runs concurrently with s2's d2 chain)
    flash_tf32_kernel<<<dim3(T_DIM / 128, H_DIM), 256, FLASH_SMEM>>>(qkv, y);

    // s2: d2 chain after q is ready
    cudaStreamWaitEvent(s2, evQ, 0);
    gemm_bf16_nt<<<dim3(M_DIM / 128, T_DIM / 128), 256, GEMM_SMEM, s2>>>(
        qbf, mkbf, S, mkn);
    topk_kernel<<<T_DIM, 256, 0, s2>>>(S);
    rescore_kernel<<<T_DIM, 384, 0, s2>>>(qkv, mem_db, mkn);
    cudaEventRecord(evJoin, s2);

    // join: memattn needs y (s0) + g_idx (s2)
    cudaStreamWaitEvent(0, evJoin, 0);
    memattn_kernel<<<T_DIM, 512>>>(qkv, mem_db, y, gate);

    // out = comb @ W_proj^T
    gemm_tf32_nt<<<dim3(1024 / 128, 2048 / 128), 256>>>(
        comb, E_DIM, W_proj, E_DIM, out, E_DIM, E_DIM);
}

// round 16
// speedup vs baseline: 1.4121x; 1.4121x over previous
#include <cuda_runtime.h>
#include <cuda_bf16.h>
#include <math_constants.h>
#include <cstdint>
#include <cstddef>

#define T_DIM 2048
#define E_DIM 1024
#define M_DIM 32768
#define H_DIM 16
#define D_DIM 64
#define KCAND 8

// ---------------- device scratch ----------------
__device__ float g_qkv[T_DIM * 3 * E_DIM];
__device__ float g_y[T_DIM * E_DIM];
__device__ float g_S[(size_t)T_DIM * M_DIM];     // 256 MB coarse scores
__device__ float g_mknorm[M_DIM];
__device__ float g_comb[T_DIM * E_DIM];
__device__ __nv_bfloat16 g_qbf[T_DIM * E_DIM];
__device__ __nv_bfloat16 g_mkbf[(size_t)M_DIM * E_DIM];

__device__ __forceinline__ uint32_t smem_u32(const void* p) {
    return (uint32_t)__cvta_generic_to_shared(p);
}
__device__ __forceinline__ uint32_t f2tf32(float f) {
    uint32_t u;
    asm("cvt.rna.tf32.f32 %0,%1;" : "=r"(u) : "f"(f));
    return u;
}
__device__ __forceinline__ float f2tf32f(float f) {
    return __uint_as_float(f2tf32(f));
}

// ---------------- fp32 SGEMM (NT) — ranking-exact q path ----
template <int WRITE_BF16>
__global__ void __launch_bounds__(256)
sgemm_nt(const float* __restrict__ A, int lda,
         const float* __restrict__ B, int ldb,
         float* __restrict__ C, int ldc, int K) {
    __shared__ float As[8][132];
    __shared__ float Bs[8][132];
    const int tid = threadIdx.x;
    const int mBase = blockIdx.y * 128;
    const int nBase = blockIdx.x * 128;
    const int lr = tid >> 1;
    const int lc = (tid & 1) << 2;
    const float* Ag = A + (size_t)(mBase + lr) * lda + lc;
    const float* Bg = B + (size_t)(nBase + lr) * ldb + lc;
    const int tm = tid >> 4;
    const int tn = tid & 15;

    float acc[8][8];
#pragma unroll
    for (int i = 0; i < 8; i++)
#pragma unroll
        for (int j = 0; j < 8; j++) acc[i][j] = 0.0f;

    for (int k0 = 0; k0 < K; k0 += 8) {
        float4 av = *(const float4*)(Ag + k0);
        float4 bv = *(const float4*)(Bg + k0);
        __syncthreads();
        As[lc + 0][lr] = av.x; As[lc + 1][lr] = av.y;
        As[lc + 2][lr] = av.z; As[lc + 3][lr] = av.w;
        Bs[lc + 0][lr] = bv.x; Bs[lc + 1][lr] = bv.y;
        Bs[lc + 2][lr] = bv.z; Bs[lc + 3][lr] = bv.w;
        __syncthreads();
#pragma unroll
        for (int kk = 0; kk < 8; kk++) {
            float a[8], b[8];
            *(float4*)&a[0] = *(const float4*)&As[kk][tm * 8];
            *(float4*)&a[4] = *(const float4*)&As[kk][tm * 8 + 4];
            *(float4*)&b[0] = *(const float4*)&Bs[kk][tn * 8];
            *(float4*)&b[4] = *(const float4*)&Bs[kk][tn * 8 + 4];
#pragma unroll
            for (int i = 0; i < 8; i++)
#pragma unroll
                for (int j = 0; j < 8; j++)
                    acc[i][j] += a[i] * b[j];
        }
    }

#pragma unroll
    for (int i = 0; i < 8; i++) {
        int row = mBase + tm * 8 + i;
        size_t roff = (size_t)row * ldc + nBase + tn * 8;
#pragma unroll
        for (int j = 0; j < 8; j += 4) {
            float4 v;
            v.x = acc[i][j]; v.y = acc[i][j + 1];
            v.z = acc[i][j + 2]; v.w = acc[i][j + 3];
            *(float4*)&C[roff + j] = v;
            if (WRITE_BF16) {
                __nv_bfloat162* o =
                    (__nv_bfloat162*)&g_qbf[(size_t)row * 1024 + nBase + tn * 8 + j];
                o[0] = __float22bfloat162_rn(make_float2(v.x, v.y));
                o[1] = __float22bfloat162_rn(make_float2(v.z, v.w));
            }
        }
    }
}

// ---------------- tf32 tensor-core NT GEMM: C = A B^T ----------------
__global__ void __launch_bounds__(256)
gemm_tf32_nt(const float* __restrict__ A, int lda,
             const float* __restrict__ B, int ldb,
             float* __restrict__ C, int ldc, int K) {
    __shared__ float As[2][128 * 20];
    __shared__ float Bs[2][128 * 20];
    const int tid = threadIdx.x;
    const int mBase = blockIdx.y * 128;
    const int nBase = blockIdx.x * 128;
    const int lrow = tid >> 2;
    const int k4 = (tid & 3) * 4;
    const int warp = tid >> 5, lane = tid & 31;
    const int wm = warp & 3, wn = warp >> 2;

    float acc[2][8][4];
#pragma unroll
    for (int a = 0; a < 2; a++)
#pragma unroll
        for (int b = 0; b < 8; b++)
#pragma unroll
            for (int c = 0; c < 4; c++) acc[a][b][c] = 0.0f;

#define GL_STAGE(st, k0)                                                        \
    {                                                                           \
        _Pragma("unroll")                                                       \
        for (int half = 0; half < 2; half++) {                                  \
            int row = lrow + half * 64;                                         \
            uint32_t sa = smem_u32(&As[st][row * 20 + k4]);                     \
            const void* ga = A + (size_t)(mBase + row) * lda + (k0) + k4;       \
            asm volatile("cp.async.cg.shared.global [%0],[%1],16;\n"            \
                         :: "r"(sa), "l"(ga));                                  \
            uint32_t sb = smem_u32(&Bs[st][row * 20 + k4]);                     \
            const void* gb = B + (size_t)(nBase + row) * ldb + (k0) + k4;       \
            asm volatile("cp.async.cg.shared.global [%0],[%1],16;\n"            \
                         :: "r"(sb), "l"(gb));                                  \
        }                                                                       \
        asm volatile("cp.async.commit_group;\n");                               \
    }

    GL_STAGE(0, 0)
    const int KS = K / 16;
    for (int ks = 0; ks < KS; ks++) {
        if (ks + 1 < KS) {
            GL_STAGE((ks + 1) & 1, (ks + 1) * 16)
            asm volatile("cp.async.wait_group 1;\n");
        } else {
            asm volatile("cp.async.wait_group 0;\n");
        }
        __syncthreads();
        const float* as = As[ks & 1];
        const float* bs = Bs[ks & 1];
#pragma unroll
        for (int kk = 0; kk < 16; kk += 8) {
            uint32_t af[2][4], bf[8][2];
#pragma unroll
            for (int mt = 0; mt < 2; mt++) {
                int r0 = wm * 32 + mt * 16 + (lane >> 2);
                int c0 = kk + (lane & 3);
                af[mt][0] = f2tf32(as[r0 * 20 + c0]);
                af[mt][1] = f2tf32(as[(r0 + 8) * 20 + c0]);
                af[mt][2] = f2tf32(as[r0 * 20 + c0 + 4]);
                af[mt][3] = f2tf32(as[(r0 + 8) * 20 + c0 + 4]);
            }
#pragma unroll
            for (int nt = 0; nt < 8; nt++) {
                int n0 = wn * 64 + nt * 8 + (lane >> 2);
                int c0 = kk + (lane & 3);
                bf[nt][0] = f2tf32(bs[n0 * 20 + c0]);
                bf[nt][1] = f2tf32(bs[n0 * 20 + c0 + 4]);
            }
#pragma unroll
            for (int mt = 0; mt < 2; mt++)
#pragma unroll
                for (int nt = 0; nt < 8; nt++)
                    asm volatile(
                        "mma.sync.aligned.m16n8k8.row.col.f32.tf32.tf32.f32 "
                        "{%0,%1,%2,%3},{%4,%5,%6,%7},{%8,%9},{%0,%1,%2,%3};\n"
                        : "+f"(acc[mt][nt][0]), "+f"(acc[mt][nt][1]),
                          "+f"(acc[mt][nt][2]), "+f"(acc[mt][nt][3])
                        : "r"(af[mt][0]), "r"(af[mt][1]),
                          "r"(af[mt][2]), "r"(af[mt][3]),
                          "r"(bf[nt][0]), "r"(bf[nt][1]));
        }
        __syncthreads();
    }

    const int r = lane >> 2, c = (lane & 3) * 2;
#pragma unroll
    for (int mt = 0; mt < 2; mt++) {
#pragma unroll
        for (int nt = 0; nt < 8; nt++) {
            int row0 = mBase + wm * 32 + mt * 16 + r;
            int col = nBase + wn * 64 + nt * 8 + c;
            *(float2*)&C[(size_t)row0 * ldc + col] =
                make_float2(acc[mt][nt][0], acc[mt][nt][1]);
            *(float2*)&C[(size_t)(row0 + 8) * ldc + col] =
                make_float2(acc[mt][nt][2], acc[mt][nt][3]);
        }
    }
#undef GL_STAGE
}

// ---------------- fused: mem-key bf16 convert + |mk|^2 ----
__global__ void __launch_bounds__(256)
cvtmk_norm_kernel(const float* __restrict__ mem_db,
                  __nv_bfloat16* __restrict__ kb) {
    __shared__ float ws[8];
    const int row = blockIdx.x;
    const int tid = threadIdx.x;
    float4 v = ((const float4*)(mem_db + (size_t)row * 2048))[tid];
    __nv_bfloat162* o = (__nv_bfloat162*)(kb + (size_t)row * 1024 + tid * 4);
    o[0] = __float22bfloat162_rn(make_float2(v.x, v.y));
    o[1] = __float22bfloat162_rn(make_float2(v.z, v.w));
    float s = v.x * v.x + v.y * v.y + v.z * v.z + v.w * v.w;
#pragma unroll
    for (int off = 16; off; off >>= 1) s += __shfl_xor_sync(0xffffffffu, s, off);
    if ((tid & 31) == 0) ws[tid >> 5] = s;
    __syncthreads();
    if (tid == 0) {
        float t = 0.0f;
#pragma unroll
        for (int w = 0; w < 8; w++) t += ws[w];
        g_mknorm[row] = t;
    }
}

// ---------------- bf16 NT GEMM (d2 coarse scores), S = -2 A B^T + bias ----
#define SROW 72                              // 64 data + 8 pad bf16 elems
#define STAGE_BYTES (128 * SROW * 2)         // 18432 B per operand per stage

__global__ void __launch_bounds__(256)
gemm_bf16_nt(const __nv_bfloat16* __restrict__ A,
             const __nv_bfloat16* __restrict__ B,
             float* __restrict__ C,
             const float* __restrict__ bias) {
    extern __shared__ __align__(16) char gsm[];
    __nv_bfloat16* Abuf = (__nv_bfloat16*)gsm;
    __nv_bfloat16* Bbuf = (__nv_bfloat16*)(gsm + 2 * STAGE_BYTES);

    const int tid = threadIdx.x;
    const int mBase = blockIdx.y * 128;
    const int nBase = blockIdx.x * 128;
    const int warp = tid >> 5, lane = tid & 31;
    const int wm = warp & 1, wn = warp >> 1;

    float acc[4][4][4];
#pragma unroll
    for (int a = 0; a < 4; a++)
#pragma unroll
        for (int b = 0; b < 4; b++)
#pragma unroll
            for (int c = 0; c < 4; c++) acc[a][b][c] = 0.0f;

#define LOAD_STAGE(ks)                                                          \
    {                                                                           \
        const int _st = (ks) & 1;                                               \
        __nv_bfloat16* _as = Abuf + _st * (128 * SROW);                         \
        __nv_bfloat16* _bs = Bbuf + _st * (128 * SROW);                         \
        _Pragma("unroll")                                                       \
        for (int _i = 0; _i < 4; _i++) {                                        \
            int _idx = tid + _i * 256;                                          \
            int _row = _idx >> 3, _ch = _idx & 7;                               \
            uint32_t _sa = smem_u32(_as + _row * SROW + _ch * 8);               \
            const void* _ga = A + (size_t)(mBase + _row) * 1024 + (ks) * 64 + _ch * 8; \
            asm volatile("cp.async.cg.shared.global [%0],[%1],16;\n"            \
                         :: "r"(_sa), "l"(_ga));                                \
            uint32_t _sb = smem_u32(_bs + _row * SROW + _ch * 8);               \
            const void* _gb = B + (size_t)(nBase + _row) * 1024 + (ks) * 64 + _ch * 8; \
            asm volatile("cp.async.cg.shared.global [%0],[%1],16;\n"            \
                         :: "r"(_sb), "l"(_gb));                                \
        }                                                                       \
        asm volatile("cp.async.commit_group;\n");                               \
    }

    LOAD_STAGE(0)

    for (int ks = 0; ks < 16; ks++) {
        if (ks + 1 < 16) {
            LOAD_STAGE(ks + 1)
            asm volatile("cp.async.wait_group 1;\n");
        } else {
            asm volatile("cp.async.wait_group 0;\n");
        }
        __syncthreads();
        const __nv_bfloat16* as = Abuf + (ks & 1) * (128 * SROW);
        const __nv_bfloat16* bs = Bbuf + (ks & 1) * (128 * SROW);
#pragma unroll
        for (int kk = 0; kk < 64; kk += 16) {
            uint32_t af[4][4], bf[4][2];
#pragma unroll
            for (int mt = 0; mt < 4; mt++) {
                int base = wm * 64 + mt * 16;
                int r = lane & 7;
                int sel = lane >> 3;
                int row = base + ((sel & 1) ? 8 : 0) + r;
                int col = kk + ((sel & 2) ? 8 : 0);
                uint32_t addr = smem_u32(&as[row * SROW + col]);
                asm volatile(
                    "ldmatrix.sync.aligned.m8n8.x4.shared.b16 {%0,%1,%2,%3},[%4];\n"
                    : "=r"(af[mt][0]), "=r"(af[mt][1]),
                      "=r"(af[mt][2]), "=r"(af[mt][3])
                    : "r"(addr));
            }
#pragma unroll
            for (int np = 0; np < 2; np++) {
                int r = lane & 7;
                int sel = lane >> 3;
                int row = wn * 32 + np * 16 + ((sel >> 1) ? 8 : 0) + r;
                int col = kk + ((sel & 1) ? 8 : 0);
                uint32_t addr = smem_u32(&bs[row * SROW + col]);
                asm volatile(
                    "ldmatrix.sync.aligned.m8n8.x4.shared.b16 {%0,%1,%2,%3},[%4];\n"
                    : "=r"(bf[2 * np][0]), "=r"(bf[2 * np][1]),
                      "=r"(bf[2 * np + 1][0]), "=r"(bf[2 * np + 1][1])
                    : "r"(addr));
            }
#pragma unroll
            for (int mt = 0; mt < 4; mt++)
#pragma unroll
                for (int nt = 0; nt < 4; nt++)
                    asm volatile(
                        "mma.sync.aligned.m16n8k16.row.col.f32.bf16.bf16.f32 "
                        "{%0,%1,%2,%3},{%4,%5,%6,%7},{%8,%9},{%0,%1,%2,%3};\n"
                        : "+f"(acc[mt][nt][0]), "+f"(acc[mt][nt][1]),
                          "+f"(acc[mt][nt][2]), "+f"(acc[mt][nt][3])
                        : "r"(af[mt][0]), "r"(af[mt][1]),
                          "r"(af[mt][2]), "r"(af[mt][3]),
                          "r"(bf[nt][0]), "r"(bf[nt][1]));
        }
        __syncthreads();
    }

    const int r = lane >> 2, c = (lane & 3) * 2;
#pragma unroll
    for (int mt = 0; mt < 4; mt++) {
#pragma unroll
        for (int nt = 0; nt < 4; nt++) {
            int row0 = mBase + wm * 64 + mt * 16 + r;
            int col = nBase + wn * 32 + nt * 8 + c;
            float b0 = bias[col], b1 = bias[col + 1];
            size_t o0 = (size_t)row0 * M_DIM + col;
            float2 v0 = make_float2(-2.0f * acc[mt][nt][0] + b0,
                                    -2.0f * acc[mt][nt][1] + b1);
            *(float2*)&C[o0] = v0;
            size_t o1 = o0 + (size_t)8 * M_DIM;
            float2 v1 = make_float2(-2.0f * acc[mt][nt][2] + b0,
                                    -2.0f * acc[mt][nt][3] + b1);
            *(float2*)&C[o1] = v1;
        }
    }
#undef LOAD_STAGE
}

// ---------------- causal flash attention, warp-local softmax --------------
__global__ void __launch_bounds__(256, 2)
flash_tf32_kernel(const float* __restrict__ qkv, float* __restrict__ y) {
    extern __shared__ float sm[];

    const int h = blockIdx.y;
    const int qt = blockIdx.x;
    const int tid = threadIdx.x;
    const int qbase = qt * 128;
    const int LDQ = 3 * E_DIM;
    const int warp = tid >> 5, lane = tid & 31;
    const int fr = lane >> 2, fc = lane & 3;
    const int gr0 = qbase + warp * 16 + fr;

    uint32_t qf[8][4];
    {
        const float* q0p = &qkv[(size_t)gr0 * LDQ + h * 64];
        const float* q1p = q0p + 8 * LDQ;
#pragma unroll
        for (int ks = 0; ks < 8; ks++) {
            qf[ks][0] = f2tf32(q0p[ks * 8 + fc]);
            qf[ks][1] = f2tf32(q1p[ks * 8 + fc]);
            qf[ks][2] = f2tf32(q0p[ks * 8 + fc + 4]);
            qf[ks][3] = f2tf32(q1p[ks * 8 + fc + 4]);
        }
    }

    float m0 = -CUDART_INF_F, m1 = -CUDART_INF_F;
    float l0 = 0.0f, l1 = 0.0f;
    float acc[8][4];
#pragma unroll
    for (int nt = 0; nt < 8; nt++)
#pragma unroll
        for (int c = 0; c < 4; c++) acc[nt][c] = 0.0f;

    const int nkt = 2 * qt + 2;

#define FL_LOAD(kt)                                                             \
    {                                                                           \
        float* _ks = sm + ((kt) & 1) * (2 * 64 * 68);                           \
        float* _vs = _ks + 64 * 68;                                             \
        const int _kb = (kt) * 64;                                              \
        _Pragma("unroll")                                                       \
        for (int _i = 0; _i < 4; _i++) {                                        \
            int _idx = tid + _i * 256;                                          \
            int _r = _idx >> 4, _c4 = (_idx & 15) << 2;                         \
            const float* _src = qkv + (size_t)(_kb + _r) * LDQ + h * 64 + _c4;  \
            asm volatile("cp.async.cg.shared.global [%0],[%1],16;\n"            \
                :: "r"(smem_u32(_ks + _r * 68 + _c4)), "l"(_src + E_DIM));      \
            asm volatile("cp.async.cg.shared.global [%0],[%1],16;\n"            \
                :: "r"(smem_u32(_vs + _r * 68 + _c4)), "l"(_src + 2 * E_DIM));  \
        }                                                                       \
        asm volatile("cp.async.commit_group;\n");                               \
    }

    FL_LOAD(0)
    FL_LOAD(1)

    for (int kt = 0; kt < nkt; kt++) {
        const int kbase = kt * 64;
        if (kt + 1 < nkt) asm volatile("cp.async.wait_group 1;\n");
        else              asm volatile("cp.async.wait_group 0;\n");
        __syncthreads();
        const float* Ks = sm + (kt & 1) * (2 * 64 * 68);
        const float* Vs = Ks + 64 * 68;

        float p[8][4];
#pragma unroll
        for (int nt = 0; nt < 8; nt++)
#pragma unroll
            for (int c = 0; c < 4; c++) p[nt][c] = 0.0f;
#pragma unroll
        for (int ks = 0; ks < 8; ks++) {
            const int kc = ks * 8;
#pragma unroll
            for (int nt = 0; nt < 8; nt++) {
                int n0 = nt * 8 + fr;
                uint32_t b0 = __float_as_uint(Ks[n0 * 68 + kc + fc]);
                uint32_t b1 = __float_as_uint(Ks[n0 * 68 + kc + fc + 4]);
                asm volatile(
                    "mma.sync.aligned.m16n8k8.row.col.f32.tf32.tf32.f32 "
                    "{%0,%1,%2,%3},{%4,%5,%6,%7},{%8,%9},{%0,%1,%2,%3};\n"
                    : "+f"(p[nt][0]), "+f"(p[nt][1]),
                      "+f"(p[nt][2]), "+f"(p[nt][3])
                    : "r"(qf[ks][0]), "r"(qf[ks][1]),
                      "r"(qf[ks][2]), "r"(qf[ks][3]),
                      "r"(b0), "r"(b1));
            }
        }
#pragma unroll
        for (int nt = 0; nt < 8; nt++) {
            p[nt][0] *= 0.125f; p[nt][1] *= 0.125f;
            p[nt][2] *= 0.125f; p[nt][3] *= 0.125f;
        }
        if (kbase + 63 > qbase + warp * 16) {
#pragma unroll
            for (int nt = 0; nt < 8; nt++) {
                int c0 = kbase + nt * 8 + 2 * fc;
                if (c0 > gr0)     p[nt][0] = -CUDART_INF_F;
                if (c0 + 1 > gr0) p[nt][1] = -CUDART_INF_F;
                if (c0 > gr0 + 8)     p[nt][2] = -CUDART_INF_F;
                if (c0 + 1 > gr0 + 8) p[nt][3] = -CUDART_INF_F;
            }
        }
        float mx0 = -CUDART_INF_F, mx1 = -CUDART_INF_F;
#pragma unroll
        for (int nt = 0; nt < 8; nt++) {
            mx0 = fmaxf(mx0, fmaxf(p[nt][0], p[nt][1]));
            mx1 = fmaxf(mx1, fmaxf(p[nt][2], p[nt][3]));
        }
        mx0 = fmaxf(mx0, __shfl_xor_sync(0xffffffffu, mx0, 1));
        mx0 = fmaxf(mx0, __shfl_xor_sync(0xffffffffu, mx0, 2));
        mx1 = fmaxf(mx1, __shfl_xor_sync(0xffffffffu, mx1, 1));
        mx1 = fmaxf(mx1, __shfl_xor_sync(0xffffffffu, mx1, 2));
        float mn0 = fmaxf(m0, mx0), mn1 = fmaxf(m1, mx1);
        float cor0 = __expf(m0 - mn0), cor1 = __expf(m1 - mn1);
        m0 = mn0; m1 = mn1;
        float s0 = 0.0f, s1 = 0.0f;
#pragma unroll
        for (int nt = 0; nt < 8; nt++) {
            p[nt][0] = __expf(p[nt][0] - mn0);
            p[nt][1] = __expf(p[nt][1] - mn0);
            p[nt][2] = __expf(p[nt][2] - mn1);
            p[nt][3] = __expf(p[nt][3] - mn1);
            s0 += p[nt][0] + p[nt][1];
            s1 += p[nt][2] + p[nt][3];
        }
        s0 += __shfl_xor_sync(0xffffffffu, s0, 1);
        s0 += __shfl_xor_sync(0xffffffffu, s0, 2);
        s1 += __shfl_xor_sync(0xffffffffu, s1, 1);
        s1 += __shfl_xor_sync(0xffffffffu, s1, 2);
        l0 = l0 * cor0 + s0;
        l1 = l1 * cor1 + s1;
#pragma unroll
        for (int nt = 0; nt < 8; nt++) {
            acc[nt][0] *= cor0; acc[nt][1] *= cor0;
            acc[nt][2] *= cor1; acc[nt][3] *= cor1;
        }
        const int srcA = (lane & ~3) | (fc >> 1);
        const int srcC = srcA + 2;
        const bool odd = fc & 1;
#pragma unroll
        for (int ks = 0; ks < 8; ks++) {
            float t00 = __shfl_sync(0xffffffffu, p[ks][0], srcA);
            float t01 = __shfl_sync(0xffffffffu, p[ks][1], srcA);
            float t10 = __shfl_sync(0xffffffffu, p[ks][2], srcA);
            float t11 = __shfl_sync(0xffffffffu, p[ks][3], srcA);
            float u00 = __shfl_sync(0xffffffffu, p[ks][0], srcC);
            float u01 = __shfl_sync(0xffffffffu, p[ks][1], srcC);
            float u10 = __shfl_sync(0xffffffffu, p[ks][2], srcC);
            float u11 = __shfl_sync(0xffffffffu, p[ks][3], srcC);
            uint32_t a0 = __float_as_uint(odd ? t01 : t00);
            uint32_t a1 = __float_as_uint(odd ? t11 : t10);
            uint32_t a2 = __float_as_uint(odd ? u01 : u00);
            uint32_t a3 = __float_as_uint(odd ? u11 : u10);
            const int kc = ks * 8;
#pragma unroll
            for (int nt = 0; nt < 8; nt++) {
                int n0 = nt * 8 + fr;
                uint32_t b0 = __float_as_uint(Vs[(kc + fc) * 68 + n0]);
                uint32_t b1 = __float_as_uint(Vs[(kc + fc + 4) * 68 + n0]);
                asm volatile(
                    "mma.sync.aligned.m16n8k8.row.col.f32.tf32.tf32.f32 "
                    "{%0,%1,%2,%3},{%4,%5,%6,%7},{%8,%9},{%0,%1,%2,%3};\n"
                    : "+f"(acc[nt][0]), "+f"(acc[nt][1]),
                      "+f"(acc[nt][2]), "+f"(acc[nt][3])
                    : "r"(a0), "r"(a1), "r"(a2), "r"(a3),
                      "r"(b0), "r"(b1));
            }
        }
        __syncthreads();
        if (kt + 2 < nkt) FL_LOAD(kt + 2)
    }

    const float li0 = 1.0f / l0, li1 = 1.0f / l1;
#pragma unroll
    for (int nt = 0; nt < 8; nt++) {
        int c0 = h * 64 + nt * 8 + 2 * fc;
        *(float2*)&y[(size_t)gr0 * E_DIM + c0] =
            make_float2(acc[nt][0] * li0, acc[nt][1] * li0);
        *(float2*)&y[(size_t)(gr0 + 8) * E_DIM + c0] =
            make_float2(acc[nt][2] * li1, acc[nt][3] * li1);
    }
#undef FL_LOAD
}

// ---- fused: top-8 scan + exact fp32 rescore + mem-attn + gated combine ----
// block per token t, 512 threads.
__device__ __forceinline__ bool lt_pair(float v, int i, float w, int j) {
    return (v < w) || (v == w && i < j);
}

__global__ void __launch_bounds__(512)
topk_rescore_memattn_kernel(const float* __restrict__ S,
                            const float* __restrict__ qkv,
                            const float* __restrict__ mem_db,
                            const float* __restrict__ mknorm,
                            const float* __restrict__ y,
                            const float* __restrict__ gate) {
    __shared__ float sv[512][KCAND];   // 16 KB
    __shared__ int   si[512][KCAND];   // 16 KB
    __shared__ float sc[KCAND];
    __shared__ int   sidx[KCAND];
    __shared__ int   sids[3];

    const int t = blockIdx.x;
    const int tid = threadIdx.x;
    const float* row = S + (size_t)t * M_DIM;

    // ---- phase 1: exact lexicographic top-8 of the coarse scores ----
    float v[KCAND];
    int ix[KCAND];
#pragma unroll
    for (int k = 0; k < KCAND; k++) { v[k] = CUDART_INF_F; ix[k] = 0x7fffffff; }

#define T8_INSERT(val, idx)                                                     \
    if (lt_pair((val), (idx), v[KCAND - 1], ix[KCAND - 1])) {                   \
        v[KCAND - 1] = (val); ix[KCAND - 1] = (idx);                            \
        _Pragma("unroll")                                                       \
        for (int k = KCAND - 1; k > 0; k--) {                                   \
            if (lt_pair(v[k], ix[k], v[k - 1], ix[k - 1])) {                    \
                float tv = v[k]; v[k] = v[k - 1]; v[k - 1] = tv;                \
                int ti = ix[k]; ix[k] = ix[k - 1]; ix[k - 1] = ti;              \
            } else break;                                                       \
        }                                                                       \
    }

    for (int j = tid * 4; j < M_DIM; j += 2048) {
        float4 val = *(const float4*)&row[j];
        T8_INSERT(val.x, j)
        T8_INSERT(val.y, j + 1)
        T8_INSERT(val.z, j + 2)
        T8_INSERT(val.w, j + 3)
    }
#pragma unroll
    for (int k = 0; k < KCAND; k++) { sv[tid][k] = v[k]; si[tid][k] = ix[k]; }
    for (int s = 256; s > 0; s >>= 1) {
        __syncthreads();
        if (tid < s) {
#pragma unroll
            for (int k = 0; k < KCAND; k++) {
                float val = sv[tid + s][k];
                int idx = si[tid + s][k];
                T8_INSERT(val, idx)
            }
#pragma unroll
            for (int k = 0; k < KCAND; k++) { sv[tid][k] = v[k]; si[tid][k] = ix[k]; }
        }
    }
    __syncthreads();   // si[0][*] = final top-8 candidates
#undef T8_INSERT

    // ---- phase 2: exact fp32 rescore of the 8 candidates (warps 0..7) ----
    const int w = tid >> 5;
    const int lane = tid & 31;
    if (w < KCAND) {
        const int cand = si[0][w];
        const float* qrow = qkv + (size_t)t * 3 * E_DIM;
        const float* krow = mem_db + (size_t)cand * 2 * E_DIM;
        float dot = 0.0f;
#pragma unroll
        for (int c = 0; c < 8; c++) {
            int e = (lane + c * 32) * 4;
            float4 qv = *(const float4*)&qrow[e];
            float4 kv = *(const float4*)&krow[e];
            dot += qv.x * kv.x + qv.y * kv.y + qv.z * kv.z + qv.w * kv.w;
        }
#pragma unroll
        for (int o = 16; o; o >>= 1) dot += __shfl_xor_sync(0xffffffffu, dot, o);
        if (lane == 0) {
            sc[w] = mknorm[cand] - 2.0f * dot;
            sidx[w] = cand;
        }
    }
    __syncthreads();
    if (tid == 0) {
        float v0 = CUDART_INF_F, v1 = CUDART_INF_F, v2 = CUDART_INF_F;
        int i0 = 0x7fffffff, i1 = 0x7fffffff, i2 = 0x7fffffff;
#pragma unroll
        for (int k = 0; k < KCAND; k++) {
            float val = sc[k]; int idx = sidx[k];
            if (lt_pair(val, idx, v2, i2)) {
                if (lt_pair(val, idx, v1, i1)) {
                    v2 = v1; i2 = i1;
                    if (lt_pair(val, idx, v0, i0)) {
                        v1 = v0; i1 = i0; v0 = val; i0 = idx;
                    } else { v1 = val; i1 = idx; }
                } else { v2 = val; i2 = idx; }
            }
        }
        sids[0] = i0; sids[1] = i1; sids[2] = i2;
    }
    __syncthreads();

    // ---- phase 3: 3-way mem softmax + gated combine (16 warps = 16 heads) ----
    {
        const int h = w;                 // warp id 0..15 = head
        const int id0 = sids[0], id1 = sids[1], id2 = sids[2];
        const int d0 = lane * 2;
        size_t qoff = (size_t)t * 3 * E_DIM + h * 64 + d0;
        float q0 = qkv[qoff], q1 = qkv[qoff + 1];

        const float* k0p = mem_db + (size_t)id0 * 2 * E_DIM + h * 64;
        const float* k1p = mem_db + (size_t)id1 * 2 * E_DIM + h * 64;
        const float* k2p = mem_db + (size_t)id2 * 2 * E_DIM + h * 64;
        float s0 = q0 * k0p[d0] + q1 * k0p[d0 + 1];
        float s1 = q0 * k1p[d0] + q1 * k1p[d0 + 1];
        float s2 = q0 * k2p[d0] + q1 * k2p[d0 + 1];
#pragma unroll
        for (int o = 16; o; o >>= 1) {
            s0 += __shfl_xor_sync(0xffffffffu, s0, o);
            s1 += __shfl_xor_sync(0xffffffffu, s1, o);
            s2 += __shfl_xor_sync(0xffffffffu, s2, o);
        }
        s0 *= 4096.0f; s1 *= 4096.0f; s2 *= 4096.0f;
        float m = fmaxf(s0, fmaxf(s1, s2));
        float e0 = expf(s0 - m), e1 = expf(s1 - m), e2 = expf(s2 - m);
        float inv = 1.0f / (e0 + e1 + e2);
        e0 *= inv; e1 *= inv; e2 *= inv;

        const float* v0p = k0p + E_DIM;
        const float* v1p = k1p + E_DIM;
        const float* v2p = k2p + E_DIM;
        float o0 = e0 * v0p[d0] + e1 * v1p[d0] + e2 * v2p[d0];
        float o1 = e0 * v0p[d0 + 1] + e1 * v1p[d0 + 1] + e2 * v2p[d0 + 1];

        float g = gate[h];
        size_t off = (size_t)t * E_DIM + h * 64 + d0;
        g_comb[off]     = o0 * g + y[off] * (1.0f - g);
        g_comb[off + 1] = o1 * g + y[off + 1] * (1.0f - g);
    }
}

// ---------------- launch (fork/join concurrency) ----------------
extern "C" void kernel_launch(void* const* d_in, const int* in_sizes, int n_in,
                              void* d_out, int out_size) {
    const float* x = nullptr;
    const float* mem_db = nullptr;
    const float* W_attn = nullptr;
    const float* W_proj = nullptr;
    const float* gate = nullptr;
    for (int i = 0; i < n_in; i++) {
        switch (in_sizes[i]) {
            case 2048 * 1024:       x      = (const float*)d_in[i]; break;
            case 32768 * 2048:      mem_db = (const float*)d_in[i]; break;
            case 3072 * 1024:       W_attn = (const float*)d_in[i]; break;
            case 1024 * 1024:       W_proj = (const float*)d_in[i]; break;
            case 16:                gate   = (const float*)d_in[i]; break;
            default: break;
        }
    }
    float* out = (float*)d_out;

    void *p_qkv, *p_y, *p_S, *p_comb, *p_mkn, *p_qbf, *p_mkbf;
    cudaGetSymbolAddress(&p_qkv, g_qkv);
    cudaGetSymbolAddress(&p_y, g_y);
    cudaGetSymbolAddress(&p_S, g_S);
    cudaGetSymbolAddress(&p_comb, g_comb);
    cudaGetSymbolAddress(&p_mkn, g_mknorm);
    cudaGetSymbolAddress(&p_qbf, g_qbf);
    cudaGetSymbolAddress(&p_mkbf, g_mkbf);
    float* qkv = (float*)p_qkv;
    float* y = (float*)p_y;
    float* S = (float*)p_S;
    float* comb = (float*)p_comb;
    float* mkn = (float*)p_mkn;
    __nv_bfloat16* qbf = (__nv_bfloat16*)p_qbf;
    __nv_bfloat16* mkbf = (__nv_bfloat16*)p_mkbf;

    static cudaStream_t s2 = nullptr;
    static cudaEvent_t evFork = nullptr, evQ = nullptr, evFlash = nullptr,
                       evJoin = nullptr;
    if (s2 == nullptr) {
        cudaStreamCreateWithFlags(&s2, cudaStreamNonBlocking);
        cudaEventCreateWithFlags(&evFork, cudaEventDisableTiming);
        cudaEventCreateWithFlags(&evQ, cudaEventDisableTiming);
        cudaEventCreateWithFlags(&evFlash, cudaEventDisableTiming);
        cudaEventCreateWithFlags(&evJoin, cudaEventDisableTiming);
    }

    const int FLASH_SMEM = 4 * 64 * 68 * 4;   // 69632 B
    cudaFuncSetAttribute(flash_tf32_kernel,
                         cudaFuncAttributeMaxDynamicSharedMemorySize, FLASH_SMEM);
    const int GEMM_SMEM = 4 * STAGE_BYTES;    // 73728 B (2-stage, K-chunk 64)
    cudaFuncSetAttribute(gemm_bf16_nt,
                         cudaFuncAttributeMaxDynamicSharedMemorySize, GEMM_SMEM);

    // ---- fork side stream s2 off the capture (default) stream ----
    cudaEventRecord(evFork, 0);
    cudaStreamWaitEvent(s2, evFork, 0);

    // s2: mem-key convert + norms (needs only mem_db)
    cvtmk_norm_kernel<<<M_DIM, 256, 0, s2>>>(mem_db, mkbf);

    // s0: q = x @ W_attn[0:1024]^T  (fp32 — also emits q bf16)
    sgemm_nt<1><<<dim3(1024 / 128, 2048 / 128), 256>>>(
        x, E_DIM, W_attn, E_DIM, qkv, 3 * E_DIM, E_DIM);
    cudaEventRecord(evQ, 0);

    // s0: k,v = x @ W_attn[1024:3072]^T  (tf32)
    gemm_tf32_nt<<<dim3(2048 / 128, 2048 / 128), 256>>>(
        x, E_DIM, W_attn + (size_t)E_DIM * E_DIM, E_DIM,
        qkv + E_DIM, 3 * E_DIM, E_DIM);

    // s0: causal attention -> y  (runs concurrently with s2's d2 chain)
    flash_tf32_kernel<<<dim3(T_DIM / 128, H_DIM), 256, FLASH_SMEM>>>(qkv, y);
    cudaEventRecord(evFlash, 0);

    // s2: d2 coarse GEMM after q is ready
    cudaStreamWaitEvent(s2, evQ, 0);
    gemm_bf16_nt<<<dim3(M_DIM / 128, T_DIM / 128), 256, GEMM_SMEM, s2>>>(
        qbf, mkbf, S, mkn);
    // fused top8 + rescore + memattn needs y as well
    cudaStreamWaitEvent(s2, evFlash, 0);
    topk_rescore_memattn_kernel<<<T_DIM, 512, 0, s2>>>(
        S, qkv, mem_db, mkn, y, gate);
    cudaEventRecord(evJoin, s2);

    // join: proj needs comb (s2)
    cudaStreamWaitEvent(0, evJoin, 0);
    gemm_tf32_nt<<<dim3(1024 / 128, 2048 / 128), 256>>>(
        comb, E_DIM, W_proj, E_DIM, out, E_DIM, E_DIM);
}

// round 17
// speedup vs baseline: 1.6771x; 1.1877x over previous
#include <cuda_runtime.h>
#include <cuda_bf16.h>
#include <math_constants.h>
#include <cstdint>
#include <cstddef>

#define T_DIM 2048
#define E_DIM 1024
#define M_DIM 32768
#define H_DIM 16
#define D_DIM 64
#define KCAND 8

// ---------------- device scratch ----------------
__device__ float g_qkv[T_DIM * 3 * E_DIM];
__device__ float g_y[T_DIM * E_DIM];
__device__ float g_S[(size_t)T_DIM * M_DIM];     // 256 MB coarse scores
__device__ float g_mknorm[M_DIM];
__device__ int   g_cand[T_DIM * KCAND];
__device__ int   g_idx[T_DIM * 3];
__device__ float g_comb[T_DIM * E_DIM];
__device__ __nv_bfloat16 g_qbf[T_DIM * E_DIM];
__device__ __nv_bfloat16 g_mkbf[(size_t)M_DIM * E_DIM];

__device__ __forceinline__ uint32_t smem_u32(const void* p) {
    return (uint32_t)__cvta_generic_to_shared(p);
}
__device__ __forceinline__ uint32_t f2tf32(float f) {
    uint32_t u;
    asm("cvt.rna.tf32.f32 %0,%1;" : "=r"(u) : "f"(f));
    return u;
}
__device__ __forceinline__ float f2tf32f(float f) {
    return __uint_as_float(f2tf32(f));
}

// ---------------- fp32 SGEMM (NT) — ranking-exact q path ----
__global__ void __launch_bounds__(256)
sgemm_nt(const float* __restrict__ A, int lda,
         const float* __restrict__ B, int ldb,
         float* __restrict__ C, int ldc, int K) {
    __shared__ float As[8][132];
    __shared__ float Bs[8][132];
    const int tid = threadIdx.x;
    const int mBase = blockIdx.y * 128;
    const int nBase = blockIdx.x * 128;
    const int lr = tid >> 1;
    const int lc = (tid & 1) << 2;
    const float* Ag = A + (size_t)(mBase + lr) * lda + lc;
    const float* Bg = B + (size_t)(nBase + lr) * ldb + lc;
    const int tm = tid >> 4;
    const int tn = tid & 15;

    float acc[8][8];
#pragma unroll
    for (int i = 0; i < 8; i++)
#pragma unroll
        for (int j = 0; j < 8; j++) acc[i][j] = 0.0f;

    for (int k0 = 0; k0 < K; k0 += 8) {
        float4 av = *(const float4*)(Ag + k0);
        float4 bv = *(const float4*)(Bg + k0);
        __syncthreads();
        As[lc + 0][lr] = av.x; As[lc + 1][lr] = av.y;
        As[lc + 2][lr] = av.z; As[lc + 3][lr] = av.w;
        Bs[lc + 0][lr] = bv.x; Bs[lc + 1][lr] = bv.y;
        Bs[lc + 2][lr] = bv.z; Bs[lc + 3][lr] = bv.w;
        __syncthreads();
#pragma unroll
        for (int kk = 0; kk < 8; kk++) {
            float a[8], b[8];
            *(float4*)&a[0] = *(const float4*)&As[kk][tm * 8];
            *(float4*)&a[4] = *(const float4*)&As[kk][tm * 8 + 4];
            *(float4*)&b[0] = *(const float4*)&Bs[kk][tn * 8];
            *(float4*)&b[4] = *(const float4*)&Bs[kk][tn * 8 + 4];
#pragma unroll
            for (int i = 0; i < 8; i++)
#pragma unroll
                for (int j = 0; j < 8; j++)
                    acc[i][j] += a[i] * b[j];
        }
    }

#pragma unroll
    for (int i = 0; i < 8; i++) {
        int row = mBase + tm * 8 + i;
        size_t roff = (size_t)row * ldc + nBase + tn * 8;
#pragma unroll
        for (int j = 0; j < 8; j += 4) {
            float4 v;
            v.x = acc[i][j]; v.y = acc[i][j + 1];
            v.z = acc[i][j + 2]; v.w = acc[i][j + 3];
            *(float4*)&C[roff + j] = v;
        }
    }
}

// ---------------- tf32 tensor-core NT GEMM: C = A B^T ----------------
// OUT_BF16: C is bf16 with ldc (for the coarse-q path); else fp32.
template <int OUT_BF16>
__global__ void __launch_bounds__(256)
gemm_tf32_nt(const float* __restrict__ A, int lda,
             const float* __restrict__ B, int ldb,
             void* __restrict__ Cv, int ldc, int K) {
    __shared__ float As[2][128 * 20];
    __shared__ float Bs[2][128 * 20];
    const int tid = threadIdx.x;
    const int mBase = blockIdx.y * 128;
    const int nBase = blockIdx.x * 128;
    const int lrow = tid >> 2;
    const int k4 = (tid & 3) * 4;
    const int warp = tid >> 5, lane = tid & 31;
    const int wm = warp & 3, wn = warp >> 2;

    float acc[2][8][4];
#pragma unroll
    for (int a = 0; a < 2; a++)
#pragma unroll
        for (int b = 0; b < 8; b++)
#pragma unroll
            for (int c = 0; c < 4; c++) acc[a][b][c] = 0.0f;

#define GL_STAGE(st, k0)                                                        \
    {                                                                           \
        _Pragma("unroll")                                                       \
        for (int half = 0; half < 2; half++) {                                  \
            int row = lrow + half * 64;                                         \
            uint32_t sa = smem_u32(&As[st][row * 20 + k4]);                     \
            const void* ga = A + (size_t)(mBase + row) * lda + (k0) + k4;       \
            asm volatile("cp.async.cg.shared.global [%0],[%1],16;\n"            \
                         :: "r"(sa), "l"(ga));                                  \
            uint32_t sb = smem_u32(&Bs[st][row * 20 + k4]);                     \
            const void* gb = B + (size_t)(nBase + row) * ldb + (k0) + k4;       \
            asm volatile("cp.async.cg.shared.global [%0],[%1],16;\n"            \
                         :: "r"(sb), "l"(gb));                                  \
        }                                                                       \
        asm volatile("cp.async.commit_group;\n");                               \
    }

    GL_STAGE(0, 0)
    const int KS = K / 16;
    for (int ks = 0; ks < KS; ks++) {
        if (ks + 1 < KS) {
            GL_STAGE((ks + 1) & 1, (ks + 1) * 16)
            asm volatile("cp.async.wait_group 1;\n");
        } else {
            asm volatile("cp.async.wait_group 0;\n");
        }
        __syncthreads();
        const float* as = As[ks & 1];
        const float* bs = Bs[ks & 1];
#pragma unroll
        for (int kk = 0; kk < 16; kk += 8) {
            uint32_t af[2][4], bf[8][2];
#pragma unroll
            for (int mt = 0; mt < 2; mt++) {
                int r0 = wm * 32 + mt * 16 + (lane >> 2);
                int c0 = kk + (lane & 3);
                af[mt][0] = f2tf32(as[r0 * 20 + c0]);
                af[mt][1] = f2tf32(as[(r0 + 8) * 20 + c0]);
                af[mt][2] = f2tf32(as[r0 * 20 + c0 + 4]);
                af[mt][3] = f2tf32(as[(r0 + 8) * 20 + c0 + 4]);
            }
#pragma unroll
            for (int nt = 0; nt < 8; nt++) {
                int n0 = wn * 64 + nt * 8 + (lane >> 2);
                int c0 = kk + (lane & 3);
                bf[nt][0] = f2tf32(bs[n0 * 20 + c0]);
                bf[nt][1] = f2tf32(bs[n0 * 20 + c0 + 4]);
            }
#pragma unroll
            for (int mt = 0; mt < 2; mt++)
#pragma unroll
                for (int nt = 0; nt < 8; nt++)
                    asm volatile(
                        "mma.sync.aligned.m16n8k8.row.col.f32.tf32.tf32.f32 "
                        "{%0,%1,%2,%3},{%4,%5,%6,%7},{%8,%9},{%0,%1,%2,%3};\n"
                        : "+f"(acc[mt][nt][0]), "+f"(acc[mt][nt][1]),
                          "+f"(acc[mt][nt][2]), "+f"(acc[mt][nt][3])
                        : "r"(af[mt][0]), "r"(af[mt][1]),
                          "r"(af[mt][2]), "r"(af[mt][3]),
                          "r"(bf[nt][0]), "r"(bf[nt][1]));
        }
        __syncthreads();
    }

    const int r = lane >> 2, c = (lane & 3) * 2;
#pragma unroll
    for (int mt = 0; mt < 2; mt++) {
#pragma unroll
        for (int nt = 0; nt < 8; nt++) {
            int row0 = mBase + wm * 32 + mt * 16 + r;
            int col = nBase + wn * 64 + nt * 8 + c;
            if (OUT_BF16) {
                __nv_bfloat16* C = (__nv_bfloat16*)Cv;
                *(__nv_bfloat162*)&C[(size_t)row0 * ldc + col] =
                    __float22bfloat162_rn(
                        make_float2(acc[mt][nt][0], acc[mt][nt][1]));
                *(__nv_bfloat162*)&C[(size_t)(row0 + 8) * ldc + col] =
                    __float22bfloat162_rn(
                        make_float2(acc[mt][nt][2], acc[mt][nt][3]));
            } else {
                float* C = (float*)Cv;
                *(float2*)&C[(size_t)row0 * ldc + col] =
                    make_float2(acc[mt][nt][0], acc[mt][nt][1]);
                *(float2*)&C[(size_t)(row0 + 8) * ldc + col] =
                    make_float2(acc[mt][nt][2], acc[mt][nt][3]);
            }
        }
    }
#undef GL_STAGE
}

// ---------------- fused: mem-key bf16 convert + |mk|^2 ----
__global__ void __launch_bounds__(256)
cvtmk_norm_kernel(const float* __restrict__ mem_db,
                  __nv_bfloat16* __restrict__ kb) {
    __shared__ float ws[8];
    const int row = blockIdx.x;
    const int tid = threadIdx.x;
    float4 v = ((const float4*)(mem_db + (size_t)row * 2048))[tid];
    __nv_bfloat162* o = (__nv_bfloat162*)(kb + (size_t)row * 1024 + tid * 4);
    o[0] = __float22bfloat162_rn(make_float2(v.x, v.y));
    o[1] = __float22bfloat162_rn(make_float2(v.z, v.w));
    float s = v.x * v.x + v.y * v.y + v.z * v.z + v.w * v.w;
#pragma unroll
    for (int off = 16; off; off >>= 1) s += __shfl_xor_sync(0xffffffffu, s, off);
    if ((tid & 31) == 0) ws[tid >> 5] = s;
    __syncthreads();
    if (tid == 0) {
        float t = 0.0f;
#pragma unroll
        for (int w = 0; w < 8; w++) t += ws[w];
        g_mknorm[row] = t;
    }
}

// ---------------- bf16 NT GEMM (d2 coarse scores), S = -2 A B^T + bias ----
#define SROW 72                              // 64 data + 8 pad bf16 elems
#define STAGE_BYTES (128 * SROW * 2)         // 18432 B per operand per stage

__global__ void __launch_bounds__(256)
gemm_bf16_nt(const __nv_bfloat16* __restrict__ A,
             const __nv_bfloat16* __restrict__ B,
             float* __restrict__ C,
             const float* __restrict__ bias) {
    extern __shared__ __align__(16) char gsm[];
    __nv_bfloat16* Abuf = (__nv_bfloat16*)gsm;
    __nv_bfloat16* Bbuf = (__nv_bfloat16*)(gsm + 2 * STAGE_BYTES);

    const int tid = threadIdx.x;
    const int mBase = blockIdx.y * 128;
    const int nBase = blockIdx.x * 128;
    const int warp = tid >> 5, lane = tid & 31;
    const int wm = warp & 1, wn = warp >> 1;

    float acc[4][4][4];
#pragma unroll
    for (int a = 0; a < 4; a++)
#pragma unroll
        for (int b = 0; b < 4; b++)
#pragma unroll
            for (int c = 0; c < 4; c++) acc[a][b][c] = 0.0f;

#define LOAD_STAGE(ks)                                                          \
    {                                                                           \
        const int _st = (ks) & 1;                                               \
        __nv_bfloat16* _as = Abuf + _st * (128 * SROW);                         \
        __nv_bfloat16* _bs = Bbuf + _st * (128 * SROW);                         \
        _Pragma("unroll")                                                       \
        for (int _i = 0; _i < 4; _i++) {                                        \
            int _idx = tid + _i * 256;                                          \
            int _row = _idx >> 3, _ch = _idx & 7;                               \
            uint32_t _sa = smem_u32(_as + _row * SROW + _ch * 8);               \
            const void* _ga = A + (size_t)(mBase + _row) * 1024 + (ks) * 64 + _ch * 8; \
            asm volatile("cp.async.cg.shared.global [%0],[%1],16;\n"            \
                         :: "r"(_sa), "l"(_ga));                                \
            uint32_t _sb = smem_u32(_bs + _row * SROW + _ch * 8);               \
            const void* _gb = B + (size_t)(nBase + _row) * 1024 + (ks) * 64 + _ch * 8; \
            asm volatile("cp.async.cg.shared.global [%0],[%1],16;\n"            \
                         :: "r"(_sb), "l"(_gb));                                \
        }                                                                       \
        asm volatile("cp.async.commit_group;\n");                               \
    }

    LOAD_STAGE(0)

    for (int ks = 0; ks < 16; ks++) {
        if (ks + 1 < 16) {
            LOAD_STAGE(ks + 1)
            asm volatile("cp.async.wait_group 1;\n");
        } else {
            asm volatile("cp.async.wait_group 0;\n");
        }
        __syncthreads();
        const __nv_bfloat16* as = Abuf + (ks & 1) * (128 * SROW);
        const __nv_bfloat16* bs = Bbuf + (ks & 1) * (128 * SROW);
#pragma unroll
        for (int kk = 0; kk < 64; kk += 16) {
            uint32_t af[4][4], bf[4][2];
#pragma unroll
            for (int mt = 0; mt < 4; mt++) {
                int base = wm * 64 + mt * 16;
                int r = lane & 7;
                int sel = lane >> 3;
                int row = base + ((sel & 1) ? 8 : 0) + r;
                int col = kk + ((sel & 2) ? 8 : 0);
                uint32_t addr = smem_u32(&as[row * SROW + col]);
                asm volatile(
                    "ldmatrix.sync.aligned.m8n8.x4.shared.b16 {%0,%1,%2,%3},[%4];\n"
                    : "=r"(af[mt][0]), "=r"(af[mt][1]),
                      "=r"(af[mt][2]), "=r"(af[mt][3])
                    : "r"(addr));
            }
#pragma unroll
            for (int np = 0; np < 2; np++) {
                int r = lane & 7;
                int sel = lane >> 3;
                int row = wn * 32 + np * 16 + ((sel >> 1) ? 8 : 0) + r;
                int col = kk + ((sel & 1) ? 8 : 0);
                uint32_t addr = smem_u32(&bs[row * SROW + col]);
                asm volatile(
                    "ldmatrix.sync.aligned.m8n8.x4.shared.b16 {%0,%1,%2,%3},[%4];\n"
                    : "=r"(bf[2 * np][0]), "=r"(bf[2 * np][1]),
                      "=r"(bf[2 * np + 1][0]), "=r"(bf[2 * np + 1][1])
                    : "r"(addr));
            }
#pragma unroll
            for (int mt = 0; mt < 4; mt++)
#pragma unroll
                for (int nt = 0; nt < 4; nt++)
                    asm volatile(
                        "mma.sync.aligned.m16n8k16.row.col.f32.bf16.bf16.f32 "
                        "{%0,%1,%2,%3},{%4,%5,%6,%7},{%8,%9},{%0,%1,%2,%3};\n"
                        : "+f"(acc[mt][nt][0]), "+f"(acc[mt][nt][1]),
                          "+f"(acc[mt][nt][2]), "+f"(acc[mt][nt][3])
                        : "r"(af[mt][0]), "r"(af[mt][1]),
                          "r"(af[mt][2]), "r"(af[mt][3]),
                          "r"(bf[nt][0]), "r"(bf[nt][1]));
        }
        __syncthreads();
    }

    const int r = lane >> 2, c = (lane & 3) * 2;
#pragma unroll
    for (int mt = 0; mt < 4; mt++) {
#pragma unroll
        for (int nt = 0; nt < 4; nt++) {
            int row0 = mBase + wm * 64 + mt * 16 + r;
            int col = nBase + wn * 32 + nt * 8 + c;
            float b0 = bias[col], b1 = bias[col + 1];
            size_t o0 = (size_t)row0 * M_DIM + col;
            float2 v0 = make_float2(-2.0f * acc[mt][nt][0] + b0,
                                    -2.0f * acc[mt][nt][1] + b1);
            *(float2*)&C[o0] = v0;
            size_t o1 = o0 + (size_t)8 * M_DIM;
            float2 v1 = make_float2(-2.0f * acc[mt][nt][2] + b0,
                                    -2.0f * acc[mt][nt][3] + b1);
            *(float2*)&C[o1] = v1;
        }
    }
#undef LOAD_STAGE
}

// ---------------- causal flash attention, warp-local softmax --------------
__global__ void __launch_bounds__(256, 2)
flash_tf32_kernel(const float* __restrict__ qkv, float* __restrict__ y) {
    extern __shared__ float sm[];

    const int h = blockIdx.y;
    const int qt = blockIdx.x;
    const int tid = threadIdx.x;
    const int qbase = qt * 128;
    const int LDQ = 3 * E_DIM;
    const int warp = tid >> 5, lane = tid & 31;
    const int fr = lane >> 2, fc = lane & 3;
    const int gr0 = qbase + warp * 16 + fr;

    uint32_t qf[8][4];
    {
        const float* q0p = &qkv[(size_t)gr0 * LDQ + h * 64];
        const float* q1p = q0p + 8 * LDQ;
#pragma unroll
        for (int ks = 0; ks < 8; ks++) {
            qf[ks][0] = f2tf32(q0p[ks * 8 + fc]);
            qf[ks][1] = f2tf32(q1p[ks * 8 + fc]);
            qf[ks][2] = f2tf32(q0p[ks * 8 + fc + 4]);
            qf[ks][3] = f2tf32(q1p[ks * 8 + fc + 4]);
        }
    }

    float m0 = -CUDART_INF_F, m1 = -CUDART_INF_F;
    float l0 = 0.0f, l1 = 0.0f;
    float acc[8][4];
#pragma unroll
    for (int nt = 0; nt < 8; nt++)
#pragma unroll
        for (int c = 0; c < 4; c++) acc[nt][c] = 0.0f;

    const int nkt = 2 * qt + 2;

#define FL_LOAD(kt)                                                             \
    {                                                                           \
        float* _ks = sm + ((kt) & 1) * (2 * 64 * 68);                           \
        float* _vs = _ks + 64 * 68;                                             \
        const int _kb = (kt) * 64;                                              \
        _Pragma("unroll")                                                       \
        for (int _i = 0; _i < 4; _i++) {                                        \
            int _idx = tid + _i * 256;                                          \
            int _r = _idx >> 4, _c4 = (_idx & 15) << 2;                         \
            const float* _src = qkv + (size_t)(_kb + _r) * LDQ + h * 64 + _c4;  \
            asm volatile("cp.async.cg.shared.global [%0],[%1],16;\n"            \
                :: "r"(smem_u32(_ks + _r * 68 + _c4)), "l"(_src + E_DIM));      \
            asm volatile("cp.async.cg.shared.global [%0],[%1],16;\n"            \
                :: "r"(smem_u32(_vs + _r * 68 + _c4)), "l"(_src + 2 * E_DIM));  \
        }                                                                       \
        asm volatile("cp.async.commit_group;\n");                               \
    }

    FL_LOAD(0)
    FL_LOAD(1)

    for (int kt = 0; kt < nkt; kt++) {
        const int kbase = kt * 64;
        if (kt + 1 < nkt) asm volatile("cp.async.wait_group 1;\n");
        else              asm volatile("cp.async.wait_group 0;\n");
        __syncthreads();
        const float* Ks = sm + (kt & 1) * (2 * 64 * 68);
        const float* Vs = Ks + 64 * 68;

        float p[8][4];
#pragma unroll
        for (int nt = 0; nt < 8; nt++)
#pragma unroll
            for (int c = 0; c < 4; c++) p[nt][c] = 0.0f;
#pragma unroll
        for (int ks = 0; ks < 8; ks++) {
            const int kc = ks * 8;
#pragma unroll
            for (int nt = 0; nt < 8; nt++) {
                int n0 = nt * 8 + fr;
                uint32_t b0 = __float_as_uint(Ks[n0 * 68 + kc + fc]);
                uint32_t b1 = __float_as_uint(Ks[n0 * 68 + kc + fc + 4]);
                asm volatile(
                    "mma.sync.aligned.m16n8k8.row.col.f32.tf32.tf32.f32 "
                    "{%0,%1,%2,%3},{%4,%5,%6,%7},{%8,%9},{%0,%1,%2,%3};\n"
                    : "+f"(p[nt][0]), "+f"(p[nt][1]),
                      "+f"(p[nt][2]), "+f"(p[nt][3])
                    : "r"(qf[ks][0]), "r"(qf[ks][1]),
                      "r"(qf[ks][2]), "r"(qf[ks][3]),
                      "r"(b0), "r"(b1));
            }
        }
#pragma unroll
        for (int nt = 0; nt < 8; nt++) {
            p[nt][0] *= 0.125f; p[nt][1] *= 0.125f;
            p[nt][2] *= 0.125f; p[nt][3] *= 0.125f;
        }
        if (kbase + 63 > qbase + warp * 16) {
#pragma unroll
            for (int nt = 0; nt < 8; nt++) {
                int c0 = kbase + nt * 8 + 2 * fc;
                if (c0 > gr0)     p[nt][0] = -CUDART_INF_F;
                if (c0 + 1 > gr0) p[nt][1] = -CUDART_INF_F;
                if (c0 > gr0 + 8)     p[nt][2] = -CUDART_INF_F;
                if (c0 + 1 > gr0 + 8) p[nt][3] = -CUDART_INF_F;
            }
        }
        float mx0 = -CUDART_INF_F, mx1 = -CUDART_INF_F;
#pragma unroll
        for (int nt = 0; nt < 8; nt++) {
            mx0 = fmaxf(mx0, fmaxf(p[nt][0], p[nt][1]));
            mx1 = fmaxf(mx1, fmaxf(p[nt][2], p[nt][3]));
        }
        mx0 = fmaxf(mx0, __shfl_xor_sync(0xffffffffu, mx0, 1));
        mx0 = fmaxf(mx0, __shfl_xor_sync(0xffffffffu, mx0, 2));
        mx1 = fmaxf(mx1, __shfl_xor_sync(0xffffffffu, mx1, 1));
        mx1 = fmaxf(mx1, __shfl_xor_sync(0xffffffffu, mx1, 2));
        float mn0 = fmaxf(m0, mx0), mn1 = fmaxf(m1, mx1);
        float cor0 = __expf(m0 - mn0), cor1 = __expf(m1 - mn1);
        m0 = mn0; m1 = mn1;
        float s0 = 0.0f, s1 = 0.0f;
#pragma unroll
        for (int nt = 0; nt < 8; nt++) {
            p[nt][0] = __expf(p[nt][0] - mn0);
            p[nt][1] = __expf(p[nt][1] - mn0);
            p[nt][2] = __expf(p[nt][2] - mn1);
            p[nt][3] = __expf(p[nt][3] - mn1);
            s0 += p[nt][0] + p[nt][1];
            s1 += p[nt][2] + p[nt][3];
        }
        s0 += __shfl_xor_sync(0xffffffffu, s0, 1);
        s0 += __shfl_xor_sync(0xffffffffu, s0, 2);
        s1 += __shfl_xor_sync(0xffffffffu, s1, 1);
        s1 += __shfl_xor_sync(0xffffffffu, s1, 2);
        l0 = l0 * cor0 + s0;
        l1 = l1 * cor1 + s1;
#pragma unroll
        for (int nt = 0; nt < 8; nt++) {
            acc[nt][0] *= cor0; acc[nt][1] *= cor0;
            acc[nt][2] *= cor1; acc[nt][3] *= cor1;
        }
        const int srcA = (lane & ~3) | (fc >> 1);
        const int srcC = srcA + 2;
        const bool odd = fc & 1;
#pragma unroll
        for (int ks = 0; ks < 8; ks++) {
            float t00 = __shfl_sync(0xffffffffu, p[ks][0], srcA);
            float t01 = __shfl_sync(0xffffffffu, p[ks][1], srcA);
            float t10 = __shfl_sync(0xffffffffu, p[ks][2], srcA);
            float t11 = __shfl_sync(0xffffffffu, p[ks][3], srcA);
            float u00 = __shfl_sync(0xffffffffu, p[ks][0], srcC);
            float u01 = __shfl_sync(0xffffffffu, p[ks][1], srcC);
            float u10 = __shfl_sync(0xffffffffu, p[ks][2], srcC);
            float u11 = __shfl_sync(0xffffffffu, p[ks][3], srcC);
            uint32_t a0 = __float_as_uint(odd ? t01 : t00);
            uint32_t a1 = __float_as_uint(odd ? t11 : t10);
            uint32_t a2 = __float_as_uint(odd ? u01 : u00);
            uint32_t a3 = __float_as_uint(odd ? u11 : u10);
            const int kc = ks * 8;
#pragma unroll
            for (int nt = 0; nt < 8; nt++) {
                int n0 = nt * 8 + fr;
                uint32_t b0 = __float_as_uint(Vs[(kc + fc) * 68 + n0]);
                uint32_t b1 = __float_as_uint(Vs[(kc + fc + 4) * 68 + n0]);
                asm volatile(
                    "mma.sync.aligned.m16n8k8.row.col.f32.tf32.tf32.f32 "
                    "{%0,%1,%2,%3},{%4,%5,%6,%7},{%8,%9},{%0,%1,%2,%3};\n"
                    : "+f"(acc[nt][0]), "+f"(acc[nt][1]),
                      "+f"(acc[nt][2]), "+f"(acc[nt][3])
                    : "r"(a0), "r"(a1), "r"(a2), "r"(a3),
                      "r"(b0), "r"(b1));
            }
        }
        __syncthreads();
        if (kt + 2 < nkt) FL_LOAD(kt + 2)
    }

    const float li0 = 1.0f / l0, li1 = 1.0f / l1;
#pragma unroll
    for (int nt = 0; nt < 8; nt++) {
        int c0 = h * 64 + nt * 8 + 2 * fc;
        *(float2*)&y[(size_t)gr0 * E_DIM + c0] =
            make_float2(acc[nt][0] * li0, acc[nt][1] * li0);
        *(float2*)&y[(size_t)(gr0 + 8) * E_DIM + c0] =
            make_float2(acc[nt][2] * li1, acc[nt][3] * li1);
    }
#undef FL_LOAD
}

// ---------------- candidate top-8 (coarse scores), float4 scan ----------
__device__ __forceinline__ bool lt_pair(float v, int i, float w, int j) {
    return (v < w) || (v == w && i < j);
}

__global__ void __launch_bounds__(256) top8_kernel(const float* __restrict__ S) {
    __shared__ float sv[256][KCAND];
    __shared__ int   si[256][KCAND];
    const int t = blockIdx.x;
    const int tid = threadIdx.x;
    const float* row = S + (size_t)t * M_DIM;
    float v[KCAND];
    int ix[KCAND];
#pragma unroll
    for (int k = 0; k < KCAND; k++) { v[k] = CUDART_INF_F; ix[k] = 0x7fffffff; }

#define T8_INSERT(val, idx)                                                     \
    if (lt_pair((val), (idx), v[KCAND - 1], ix[KCAND - 1])) {                   \
        v[KCAND - 1] = (val); ix[KCAND - 1] = (idx);                            \
        _Pragma("unroll")                                                       \
        for (int k = KCAND - 1; k > 0; k--) {                                   \
            if (lt_pair(v[k], ix[k], v[k - 1], ix[k - 1])) {                    \
                float tv = v[k]; v[k] = v[k - 1]; v[k - 1] = tv;                \
                int ti = ix[k]; ix[k] = ix[k - 1]; ix[k - 1] = ti;              \
            } else break;                                                       \
        }                                                                       \
    }

    for (int j = tid * 4; j < M_DIM; j += 1024) {
        float4 val = *(const float4*)&row[j];
        T8_INSERT(val.x, j)
        T8_INSERT(val.y, j + 1)
        T8_INSERT(val.z, j + 2)
        T8_INSERT(val.w, j + 3)
    }
#pragma unroll
    for (int k = 0; k < KCAND; k++) { sv[tid][k] = v[k]; si[tid][k] = ix[k]; }
    for (int s = 128; s > 0; s >>= 1) {
        __syncthreads();
        if (tid < s) {
#pragma unroll
            for (int k = 0; k < KCAND; k++) {
                float val = sv[tid + s][k];
                int idx = si[tid + s][k];
                T8_INSERT(val, idx)
            }
#pragma unroll
            for (int k = 0; k < KCAND; k++) { sv[tid][k] = v[k]; si[tid][k] = ix[k]; }
        }
    }
    if (tid == 0) {
#pragma unroll
        for (int k = 0; k < KCAND; k++) g_cand[t * KCAND + k] = ix[k];
    }
#undef T8_INSERT
}

// ---------------- exact fp32 rescore of 8 candidates -> top-3 ------------
__global__ void __launch_bounds__(256)
rescore_kernel(const float* __restrict__ qkv,
               const float* __restrict__ mem_db,
               const float* __restrict__ mknorm) {
    __shared__ float sc[KCAND];
    __shared__ int   sidx[KCAND];
    const int t = blockIdx.x;
    const int w = threadIdx.x >> 5;
    const int lane = threadIdx.x & 31;
    const int cand = g_cand[t * KCAND + w];

    const float* qrow = qkv + (size_t)t * 3 * E_DIM;
    const float* krow = mem_db + (size_t)cand * 2 * E_DIM;
    float dot = 0.0f;
#pragma unroll
    for (int c = 0; c < 8; c++) {
        int e = (lane + c * 32) * 4;
        float4 qv = *(const float4*)&qrow[e];
        float4 kv = *(const float4*)&krow[e];
        dot += qv.x * kv.x + qv.y * kv.y + qv.z * kv.z + qv.w * kv.w;
    }
#pragma unroll
    for (int o = 16; o; o >>= 1) dot += __shfl_xor_sync(0xffffffffu, dot, o);
    if (lane == 0) {
        sc[w] = mknorm[cand] - 2.0f * dot;
        sidx[w] = cand;
    }
    __syncthreads();
    if (threadIdx.x == 0) {
        float v0 = CUDART_INF_F, v1 = CUDART_INF_F, v2 = CUDART_INF_F;
        int i0 = 0x7fffffff, i1 = 0x7fffffff, i2 = 0x7fffffff;
#pragma unroll
        for (int k = 0; k < KCAND; k++) {
            float val = sc[k]; int idx = sidx[k];
            if (lt_pair(val, idx, v2, i2)) {
                if (lt_pair(val, idx, v1, i1)) {
                    v2 = v1; i2 = i1;
                    if (lt_pair(val, idx, v0, i0)) {
                        v1 = v0; i1 = i0; v0 = val; i0 = idx;
                    } else { v1 = val; i1 = idx; }
                } else { v2 = val; i2 = idx; }
            }
        }
        g_idx[t * 3 + 0] = i0;
        g_idx[t * 3 + 1] = i1;
        g_idx[t * 3 + 2] = i2;
    }
}

// ---------------- gather + 3-way mem softmax + gated combine -------------
__global__ void __launch_bounds__(512)
memattn_kernel(const float* __restrict__ qkv,
               const float* __restrict__ mem_db,
               const float* __restrict__ y,
               const float* __restrict__ gate) {
    const int t = blockIdx.x;
    const int h = threadIdx.x >> 5;
    const int lane = threadIdx.x & 31;
    int id0 = g_idx[t * 3 + 0];
    int id1 = g_idx[t * 3 + 1];
    int id2 = g_idx[t * 3 + 2];
    const int d0 = lane * 2;
    size_t qoff = (size_t)t * 3 * E_DIM + h * 64 + d0;
    float q0 = qkv[qoff], q1 = qkv[qoff + 1];

    const float* k0p = mem_db + (size_t)id0 * 2 * E_DIM + h * 64;
    const float* k1p = mem_db + (size_t)id1 * 2 * E_DIM + h * 64;
    const float* k2p = mem_db + (size_t)id2 * 2 * E_DIM + h * 64;
    float s0 = q0 * k0p[d0] + q1 * k0p[d0 + 1];
    float s1 = q0 * k1p[d0] + q1 * k1p[d0 + 1];
    float s2 = q0 * k2p[d0] + q1 * k2p[d0 + 1];
#pragma unroll
    for (int o = 16; o; o >>= 1) {
        s0 += __shfl_xor_sync(0xffffffffu, s0, o);
        s1 += __shfl_xor_sync(0xffffffffu, s1, o);
        s2 += __shfl_xor_sync(0xffffffffu, s2, o);
    }
    s0 *= 4096.0f; s1 *= 4096.0f; s2 *= 4096.0f;
    float m = fmaxf(s0, fmaxf(s1, s2));
    float e0 = expf(s0 - m), e1 = expf(s1 - m), e2 = expf(s2 - m);
    float inv = 1.0f / (e0 + e1 + e2);
    e0 *= inv; e1 *= inv; e2 *= inv;

    const float* v0p = k0p + E_DIM;
    const float* v1p = k1p + E_DIM;
    const float* v2p = k2p + E_DIM;
    float o0 = e0 * v0p[d0] + e1 * v1p[d0] + e2 * v2p[d0];
    float o1 = e0 * v0p[d0 + 1] + e1 * v1p[d0 + 1] + e2 * v2p[d0 + 1];

    float g = gate[h];
    size_t off = (size_t)t * E_DIM + h * 64 + d0;
    g_comb[off]     = o0 * g + y[off] * (1.0f - g);
    g_comb[off + 1] = o1 * g + y[off + 1] * (1.0f - g);
}

// ---------------- launch (fork/join concurrency) ----------------
extern "C" void kernel_launch(void* const* d_in, const int* in_sizes, int n_in,
                              void* d_out, int out_size) {
    const float* x = nullptr;
    const float* mem_db = nullptr;
    const float* W_attn = nullptr;
    const float* W_proj = nullptr;
    const float* gate = nullptr;
    for (int i = 0; i < n_in; i++) {
        switch (in_sizes[i]) {
            case 2048 * 1024:       x      = (const float*)d_in[i]; break;
            case 32768 * 2048:      mem_db = (const float*)d_in[i]; break;
            case 3072 * 1024:       W_attn = (const float*)d_in[i]; break;
            case 1024 * 1024:       W_proj = (const float*)d_in[i]; break;
            case 16:                gate   = (const float*)d_in[i]; break;
            default: break;
        }
    }
    float* out = (float*)d_out;

    void *p_qkv, *p_y, *p_S, *p_comb, *p_mkn, *p_qbf, *p_mkbf;
    cudaGetSymbolAddress(&p_qkv, g_qkv);
    cudaGetSymbolAddress(&p_y, g_y);
    cudaGetSymbolAddress(&p_S, g_S);
    cudaGetSymbolAddress(&p_comb, g_comb);
    cudaGetSymbolAddress(&p_mkn, g_mknorm);
    cudaGetSymbolAddress(&p_qbf, g_qbf);
    cudaGetSymbolAddress(&p_mkbf, g_mkbf);
    float* qkv = (float*)p_qkv;
    float* y = (float*)p_y;
    float* S = (float*)p_S;
    float* comb = (float*)p_comb;
    float* mkn = (float*)p_mkn;
    __nv_bfloat16* qbf = (__nv_bfloat16*)p_qbf;
    __nv_bfloat16* mkbf = (__nv_bfloat16*)p_mkbf;

    static cudaStream_t s2 = nullptr;
    static cudaEvent_t evFork = nullptr, evQ = nullptr, evJoin = nullptr;
    if (s2 == nullptr) {
        cudaStreamCreateWithFlags(&s2, cudaStreamNonBlocking);
        cudaEventCreateWithFlags(&evFork, cudaEventDisableTiming);
        cudaEventCreateWithFlags(&evQ, cudaEventDisableTiming);
        cudaEventCreateWithFlags(&evJoin, cudaEventDisableTiming);
    }

    const int FLASH_SMEM = 4 * 64 * 68 * 4;   // 69632 B
    cudaFuncSetAttribute(flash_tf32_kernel,
                         cudaFuncAttributeMaxDynamicSharedMemorySize, FLASH_SMEM);
    const int GEMM_SMEM = 4 * STAGE_BYTES;    // 73728 B (2-stage, K-chunk 64)
    cudaFuncSetAttribute(gemm_bf16_nt,
                         cudaFuncAttributeMaxDynamicSharedMemorySize, GEMM_SMEM);

    // ---- fork side stream s2 off the capture (default) stream ----
    cudaEventRecord(evFork, 0);
    cudaStreamWaitEvent(s2, evFork, 0);

    // s2: coarse q (bf16 via tf32 GEMM) — the d2 chain's only q dependency
    gemm_tf32_nt<1><<<dim3(1024 / 128, 2048 / 128), 256, 0, s2>>>(
        x, E_DIM, W_attn, E_DIM, qbf, E_DIM, E_DIM);
    // s2: mem-key convert + norms (needs only mem_db)
    cvtmk_norm_kernel<<<M_DIM, 256, 0, s2>>>(mem_db, mkbf);
    // s2: d2 coarse GEMM + top-8 (no dependence on s0 at all)
    gemm_bf16_nt<<<dim3(M_DIM / 128, T_DIM / 128), 256, GEMM_SMEM, s2>>>(
        qbf, mkbf, S, mkn);
    top8_kernel<<<T_DIM, 256, 0, s2>>>(S);

    // s0: exact fp32 q (rescore/memattn path)
    sgemm_nt<<<dim3(1024 / 128, 2048 / 128), 256>>>(
        x, E_DIM, W_attn, E_DIM, qkv, 3 * E_DIM, E_DIM);
    cudaEventRecord(evQ, 0);
    // s0: k,v then flash
    gemm_tf32_nt<0><<<dim3(2048 / 128, 2048 / 128), 256>>>(
        x, E_DIM, W_attn + (size_t)E_DIM * E_DIM, E_DIM,
        qkv + E_DIM, 3 * E_DIM, E_DIM);
    flash_tf32_kernel<<<dim3(T_DIM / 128, H_DIM), 256, FLASH_SMEM>>>(qkv, y);

    // s2: rescore needs fp32 q from s0
    cudaStreamWaitEvent(s2, evQ, 0);
    rescore_kernel<<<T_DIM, 256, 0, s2>>>(qkv, mem_db, mkn);
    cudaEventRecord(evJoin, s2);

    // join: memattn needs y (s0) + g_idx (s2)
    cudaStreamWaitEvent(0, evJoin, 0);
    memattn_kernel<<<T_DIM, 512>>>(qkv, mem_db, y, gate);

    // out = comb @ W_proj^T
    gemm_tf32_nt<0><<<dim3(1024 / 128, 2048 / 128), 256>>>(
        comb, E_DIM, W_proj, E_DIM, out, E_DIM, E_DIM);
}